// round 5
// baseline (speedup 1.0000x reference)
#include <cuda_runtime.h>
#include <cuda_bf16.h>
#include <math.h>
#include <stdint.h>

// Problem constants
constexpr int Bv = 128, Nv = 512, Kv = 10, Fv = 128, TFv = 256, Cv = 40;

// Layer tiling: persistent CTAs, W resident in smem
constexpr int MT      = 64;                 // rows per tile
constexpr int NTILES  = (Bv * Nv) / MT;     // 1024
constexpr int GRID    = 148;                // one CTA per SM
constexpr int THREADS = 256;

constexpr int WPITCH  = 136;                // W row: 128 + 8 pad bf16 (272 B, bank skew 4)
constexpr int APITCH  = 264;                // A row: 256 + 8 pad bf16 (528 B, bank skew 4)
constexpr int W_PLANE = 128 * WPITCH * 2;   // 34816 B  (one [chunk][part] plane)
constexpr int A_PLANE = MT * APITCH * 2;    // 33792 B  (one part plane)
constexpr int W_OFF   = 0;                  // 4 planes = 139264 B
constexpr int A_OFF   = 4 * W_PLANE;        // 139264
constexpr int SMEM_BYTES = A_OFF + 2 * A_PLANE;  // 206848

// Scratch (static device globals: allocation-free rule)
__device__ float g_h1[Bv * Nv * Fv];
__device__ float g_h2[Bv * Nv * Fv];
// Pre-split padded weights, same layout as smem: [layer][chunk][part][128][WPITCH]
__device__ __align__(16) __nv_bfloat16 g_wp[2][2][2][128][WPITCH];
__device__ float g_z[Bv * 64];

// ---------------- bf16 HMMA (sm_80+ base; no 'a' target needed) ----------------
__device__ __forceinline__ void mma_bf16(float* c, const uint32_t* a,
                                         uint32_t b0, uint32_t b1) {
    asm volatile(
        "mma.sync.aligned.m16n8k16.row.col.f32.bf16.bf16.f32 "
        "{%0,%1,%2,%3}, {%4,%5,%6,%7}, {%8,%9}, {%0,%1,%2,%3};"
        : "+f"(c[0]), "+f"(c[1]), "+f"(c[2]), "+f"(c[3])
        : "r"(a[0]), "r"(a[1]), "r"(a[2]), "r"(a[3]), "r"(b0), "r"(b1));
}

// split a float4 into bf16 hi/lo packed pairs
__device__ __forceinline__ void split4(const float4 v, uint2& hi, uint2& lo) {
    __nv_bfloat16 h[4], l[4];
    const float va[4] = {v.x, v.y, v.z, v.w};
    #pragma unroll
    for (int q = 0; q < 4; ++q) {
        h[q] = __float2bfloat16(va[q]);
        l[q] = __float2bfloat16(va[q] - __bfloat162float(h[q]));
    }
    hi = *(uint2*)h;
    lo = *(uint2*)l;
}

// ---------------- prep: split + pad weights into smem-identical layout ----------------
__global__ __launch_bounds__(256) void prep_w_kernel(const float* __restrict__ w) {
    const int idx = blockIdx.x * 256 + threadIdx.x;  // 2*128*256 = 65536
    const int l = idx >> 15;
    const int r = idx & 32767;
    const int g = r >> 8;       // output row (0..127)
    const int k = r & 255;      // input col
    const float v = w[l * (TFv * Fv) + g * TFv + k];
    const __nv_bfloat16 hi = __float2bfloat16(v);
    const __nv_bfloat16 lo = __float2bfloat16(v - __bfloat162float(hi));
    const int chunk = k >> 7, kk = k & 127;
    g_wp[l][chunk][0][g][kk] = hi;
    g_wp[l][chunk][1][g][kk] = lo;
}

// ---------------- persistent fused SAGE layer ----------------
__global__ __launch_bounds__(THREADS, 1) void sage_layer_mma(
    const float* __restrict__ hin, const int* __restrict__ neigh,
    const __nv_bfloat16* __restrict__ wp,   // -> g_wp[layer]
    const float* __restrict__ bias, float* __restrict__ hout)
{
    extern __shared__ char sm[];
    const int t = threadIdx.x, lane = t & 31, warp = t >> 5;

    // ---- Stage full split weight set ONCE (139264 B, straight uint4 copy) ----
    {
        const uint4* src = (const uint4*)wp;
        uint4* dst = (uint4*)(sm + W_OFF);
        #pragma unroll
        for (int i = 0; i < 34; ++i)          // 34 * 256 = 8704 uint4 = 139264 B
            dst[t + i * 256] = __ldg(src + t + i * 256);
    }

    const int wm = (warp >> 2) * 32;          // warp m offset: 0 / 32
    const int wn = (warp & 3) * 32;           // warp n offset: 0,32,64,96
    const int qr = lane >> 2;                 // 0-7
    const int qc = (lane & 3) * 2;            // 0,2,4,6

    // ---- gather-mean stage (registers) for one tile ----
    float4 gm[8];
    auto stage_gather = [&](int tile) {
        const int row0 = tile * MT;
        #pragma unroll
        for (int j = 0; j < 8; ++j) {
            const int rowg = row0 + warp * 8 + j;
            const int b    = rowg >> 9;              // N = 512
            const int* nb  = neigh + rowg * Kv;
            float4 a4 = make_float4(0.f, 0.f, 0.f, 0.f);
            #pragma unroll
            for (int k = 0; k < Kv; ++k) {
                const int idx = __ldg(nb + k);
                const float4 v = __ldg((const float4*)(hin + (b * Nv + idx) * Fv) + lane);
                a4.x += v.x; a4.y += v.y; a4.z += v.z; a4.w += v.w;
            }
            const float inv = 1.0f / Kv;
            gm[j] = make_float4(a4.x * inv, a4.y * inv, a4.z * inv, a4.w * inv);
        }
    };

    int tile = blockIdx.x;
    stage_gather(tile);
    __syncthreads();   // W staging complete before first MMA

    for (;;) {
        // ---- write A tile: mean (cols 0-127 from regs) + self (cols 128-255) ----
        {
            const int row0 = tile * MT;
            #pragma unroll
            for (int j = 0; j < 8; ++j) {
                const int r    = warp * 8 + j;
                const int rowg = row0 + r;
                uint2 hi, lo;
                split4(gm[j], hi, lo);
                const int offm = A_OFF + r * (APITCH * 2) + lane * 8;
                *(uint2*)(sm + offm)           = hi;
                *(uint2*)(sm + offm + A_PLANE) = lo;
                const float4 hv = __ldg((const float4*)(hin + rowg * Fv) + lane);
                split4(hv, hi, lo);
                const int offs = offm + 256;   // col 128 start (128*2 B)
                *(uint2*)(sm + offs)           = hi;
                *(uint2*)(sm + offs + A_PLANE) = lo;
            }
        }
        __syncthreads();

        const int row0 = tile * MT;
        const int tn = tile + GRID;
        const bool more = tn < NTILES;
        if (more) stage_gather(tn);   // next tile's gather overlaps MMA below

        // ---- MMA: full K=256, 16 ksteps, 3 split products, 2m x 4n frags ----
        float acc[2][4][4];
        #pragma unroll
        for (int mf = 0; mf < 2; ++mf)
            #pragma unroll
            for (int nf = 0; nf < 4; ++nf)
                #pragma unroll
                for (int q = 0; q < 4; ++q) acc[mf][nf][q] = 0.f;

        #pragma unroll
        for (int ks = 0; ks < 16; ++ks) {
            const int chunk = ks >> 3;
            const int cA = (ks * 16 + qc) * 2;          // A col byte offset
            const int cW = ((ks & 7) * 16 + qc) * 2;    // W col byte offset
            uint32_t AH[2][4], AL[2][4];
            #pragma unroll
            for (int mf = 0; mf < 2; ++mf) {
                const int r0 = A_OFF + (wm + mf * 16 + qr) * (APITCH * 2);
                const int r8 = r0 + 8 * (APITCH * 2);
                AH[mf][0] = *(const uint32_t*)(sm + r0 + cA);
                AH[mf][1] = *(const uint32_t*)(sm + r8 + cA);
                AH[mf][2] = *(const uint32_t*)(sm + r0 + cA + 16);
                AH[mf][3] = *(const uint32_t*)(sm + r8 + cA + 16);
                AL[mf][0] = *(const uint32_t*)(sm + r0 + A_PLANE + cA);
                AL[mf][1] = *(const uint32_t*)(sm + r8 + A_PLANE + cA);
                AL[mf][2] = *(const uint32_t*)(sm + r0 + A_PLANE + cA + 16);
                AL[mf][3] = *(const uint32_t*)(sm + r8 + A_PLANE + cA + 16);
            }
            #pragma unroll
            for (int nf = 0; nf < 4; ++nf) {
                const int n  = wn + nf * 8 + qr;
                const int bh = W_OFF + (chunk * 2 + 0) * W_PLANE + n * (WPITCH * 2);
                const int bl = W_OFF + (chunk * 2 + 1) * W_PLANE + n * (WPITCH * 2);
                const uint32_t bh0 = *(const uint32_t*)(sm + bh + cW);
                const uint32_t bh1 = *(const uint32_t*)(sm + bh + cW + 16);
                const uint32_t bl0 = *(const uint32_t*)(sm + bl + cW);
                const uint32_t bl1 = *(const uint32_t*)(sm + bl + cW + 16);
                #pragma unroll
                for (int mf = 0; mf < 2; ++mf) {
                    mma_bf16(acc[mf][nf], AH[mf], bh0, bh1);
                    mma_bf16(acc[mf][nf], AL[mf], bh0, bh1);
                    mma_bf16(acc[mf][nf], AH[mf], bl0, bl1);
                }
            }
        }

        // ---- epilogue: + bias, store ----
        #pragma unroll
        for (int mf = 0; mf < 2; ++mf) {
            const int rA = row0 + wm + mf * 16 + qr;
            #pragma unroll
            for (int nf = 0; nf < 4; ++nf) {
                const int col = wn + nf * 8 + qc;
                const float b0 = __ldg(bias + col);
                const float b1 = __ldg(bias + col + 1);
                *(float2*)(hout + rA * Fv + col) =
                    make_float2(acc[mf][nf][0] + b0, acc[mf][nf][1] + b1);
                *(float2*)(hout + (rA + 8) * Fv + col) =
                    make_float2(acc[mf][nf][2] + b0, acc[mf][nf][3] + b1);
            }
        }
        __syncthreads();   // all MMA smem reads done before next A write
        if (!more) break;
        tile = tn;
    }
}

// ---------------- tail part 1: z = h[:,0,:] @ l1w^T + l1b ----------------
__global__ __launch_bounds__(256) void lin1_kernel(
    const float* __restrict__ h,
    const float* __restrict__ l1w, const float* __restrict__ l1b,
    float* __restrict__ z)
{
    __shared__ float red[4][64];
    const int b  = blockIdx.x;
    const int j  = threadIdx.x & 63;
    const int sl = threadIdx.x >> 6;
    const float4* hr = (const float4*)(h + b * Nv * Fv) + sl * 8;
    const float4* wr = (const float4*)(l1w + j * Fv) + sl * 8;
    float s = 0.f;
    #pragma unroll
    for (int q = 0; q < 8; ++q) {
        const float4 a = __ldg(hr + q);
        const float4 w = __ldg(wr + q);
        s = fmaf(a.x, w.x, s); s = fmaf(a.y, w.y, s);
        s = fmaf(a.z, w.z, s); s = fmaf(a.w, w.w, s);
    }
    red[sl][j] = s;
    __syncthreads();
    if (sl == 0)
        z[b * 64 + j] = red[0][j] + red[1][j] + red[2][j] + red[3][j] + __ldg(l1b + j);
}

// ---------------- tail part 2: BN -> relu -> lin2 -> softmax ----------------
__global__ __launch_bounds__(128) void tail_kernel(
    const float* __restrict__ z_in,
    const float* __restrict__ gamma, const float* __restrict__ beta,
    const float* __restrict__ l2w, const float* __restrict__ l2b,
    float* __restrict__ out)
{
    __shared__ float s_z[Bv][65];
    __shared__ float s_scale[64], s_shift[64];
    const int t = threadIdx.x;

    for (int o = t; o < Bv * 64; o += 128) s_z[o >> 6][o & 63] = z_in[o];
    __syncthreads();

    if (t < 64) {
        float mu = 0.f;
        #pragma unroll 4
        for (int b = 0; b < Bv; ++b) mu += s_z[b][t];
        mu *= (1.0f / Bv);
        float var = 0.f;
        #pragma unroll 4
        for (int b = 0; b < Bv; ++b) { const float d = s_z[b][t] - mu; var += d * d; }
        var *= (1.0f / Bv);
        const float sc = gamma[t] * rsqrtf(var + 1e-5f);
        s_scale[t] = sc;
        s_shift[t] = beta[t] - mu * sc;
    }
    __syncthreads();

    for (int o = t; o < Bv * 64; o += 128) {
        const int b = o >> 6, j = o & 63;
        s_z[b][j] = fmaxf(s_z[b][j] * s_scale[j] + s_shift[j], 0.f);
    }
    __syncthreads();

    {
        float lg[Cv];
        #pragma unroll
        for (int c = 0; c < Cv; ++c) {
            const float* wr = l2w + c * 64;
            float s = 0.f;
            #pragma unroll
            for (int j = 0; j < 64; ++j) s = fmaf(s_z[t][j], wr[j], s);
            lg[c] = s + l2b[c];
        }
        float m = lg[0];
        #pragma unroll
        for (int c = 1; c < Cv; ++c) m = fmaxf(m, lg[c]);
        float sum = 0.f;
        #pragma unroll
        for (int c = 0; c < Cv; ++c) { lg[c] = expf(lg[c] - m); sum += lg[c]; }
        const float r = 1.0f / sum;
        #pragma unroll
        for (int c = 0; c < Cv; ++c) out[t * Cv + c] = lg[c] * r;
    }
}

extern "C" void kernel_launch(void* const* d_in, const int* in_sizes, int n_in,
                              void* d_out, int out_size) {
    const float* x      = (const float*)d_in[0];
    const int*   neigh  = (const int*)  d_in[1];
    const float* w_sage = (const float*)d_in[2];
    const float* b_sage = (const float*)d_in[3];
    const float* l1w    = (const float*)d_in[4];
    const float* l1b    = (const float*)d_in[5];
    const float* gamma  = (const float*)d_in[6];
    const float* beta   = (const float*)d_in[7];
    const float* l2w    = (const float*)d_in[8];
    const float* l2b    = (const float*)d_in[9];
    float* out = (float*)d_out;

    cudaFuncSetAttribute(sage_layer_mma,
                         cudaFuncAttributeMaxDynamicSharedMemorySize, SMEM_BYTES);

    void *p1, *p2, *pw, *pz;
    cudaGetSymbolAddress(&p1, g_h1);
    cudaGetSymbolAddress(&p2, g_h2);
    cudaGetSymbolAddress(&pw, g_wp);
    cudaGetSymbolAddress(&pz, g_z);
    float* h1 = (float*)p1;
    float* h2 = (float*)p2;
    __nv_bfloat16* wb = (__nv_bfloat16*)pw;
    float* z = (float*)pz;

    prep_w_kernel<<<256, 256>>>(w_sage);

    const int wlayer = 2 * 2 * 128 * WPITCH;   // elems per layer in g_wp
    sage_layer_mma<<<GRID, THREADS, SMEM_BYTES>>>(x,  neigh, wb,          b_sage,      h1);
    sage_layer_mma<<<GRID, THREADS, SMEM_BYTES>>>(h1, neigh, wb + wlayer, b_sage + Fv, h2);

    lin1_kernel<<<Bv, 256>>>(h2, l1w, l1b, z);
    tail_kernel<<<1, 128>>>(z, gamma, beta, l2w, l2b, out);
}

// round 6
// speedup vs baseline: 2.5883x; 2.5883x over previous
#include <cuda_runtime.h>
#include <cuda_bf16.h>
#include <math.h>
#include <stdint.h>

// Problem constants
constexpr int Bv = 128, Nv = 512, Kv = 10, Fv = 128, TFv = 256, Cv = 40;

// Dependence-cone sizes (node 0, 2 layers, K=10)
constexpr int S2N = 11;              // layer-2 input nodes per b: {0} U neigh[b,0]
constexpr int S1N = 121;             // layer-1 input rows per b: 11 * 11
constexpr int NR1 = Bv * S1N;        // 15488 GEMM1 rows
constexpr int NR2 = Bv * S2N;        // 1408  GEMM2 rows
constexpr int TILES1 = NR1 / 64;     // 242
constexpr int TILES2 = NR2 / 64;     // 22

// GEMM smem layout (bytes)
constexpr int PITCH   = 136;                 // bf16 per row = 272 B (LDSM conflict-free)
constexpr int W_PLANE = 256 * PITCH * 2;     // 69632  (one split part of Wcat 256x128)
constexpr int A_OFF   = 2 * W_PLANE;         // 139264
constexpr int A_PLANE = 64 * PITCH * 2;      // 17408
constexpr int SMEM_BYTES = A_OFF + 2 * A_PLANE;  // 174080

// Scratch (static device globals: allocation-free rule)
__device__ float g_y1[NR1 * 256];
__device__ float g_y2[NR2 * 256];
__device__ float g_h1c[NR2 * 128];
__device__ int   g_list1[NR1];
__device__ float g_z[Bv * 64];
// Split concatenated weights: [layer][part hi/lo][256 out-rows][PITCH k]
__device__ __align__(16) __nv_bfloat16 g_wcat[2][2][256][PITCH];

// ---------------- HMMA / LDSM helpers (sm_75/80 base features) ----------------
__device__ __forceinline__ void mma_bf16(float* c, const uint32_t* a,
                                         uint32_t b0, uint32_t b1) {
    asm volatile(
        "mma.sync.aligned.m16n8k16.row.col.f32.bf16.bf16.f32 "
        "{%0,%1,%2,%3}, {%4,%5,%6,%7}, {%8,%9}, {%0,%1,%2,%3};"
        : "+f"(c[0]), "+f"(c[1]), "+f"(c[2]), "+f"(c[3])
        : "r"(a[0]), "r"(a[1]), "r"(a[2]), "r"(a[3]), "r"(b0), "r"(b1));
}
__device__ __forceinline__ void ldsm_x4(uint32_t* r, uint32_t addr) {
    asm volatile("ldmatrix.sync.aligned.m8n8.x4.shared.b16 {%0,%1,%2,%3}, [%4];"
                 : "=r"(r[0]), "=r"(r[1]), "=r"(r[2]), "=r"(r[3]) : "r"(addr));
}
__device__ __forceinline__ uint32_t smem_u32(const void* p) {
    uint32_t a;
    asm("{ .reg .u64 t; cvta.to.shared.u64 t, %1; cvt.u32.u64 %0, t; }"
        : "=r"(a) : "l"(p));
    return a;
}
__device__ __forceinline__ void split4(const float4 v, uint2& hi, uint2& lo) {
    __nv_bfloat16 h[4], l[4];
    const float va[4] = {v.x, v.y, v.z, v.w};
    #pragma unroll
    for (int q = 0; q < 4; ++q) {
        h[q] = __float2bfloat16(va[q]);
        l[q] = __float2bfloat16(va[q] - __bfloat162float(h[q]));
    }
    hi = *(uint2*)h;
    lo = *(uint2*)l;
}

// ---------------- prep: build split Wcat ----------------
// Wcat[l][j][k] = (j < 128) ? W[l][j][k]  (mp coefficients)
//                           : W[l][j-128][128+k]  (self coefficients)
__global__ __launch_bounds__(256) void prep_w_kernel(const float* __restrict__ w) {
    const int idx = blockIdx.x * 256 + threadIdx.x;   // 2*256*128 = 65536
    const int l = idx >> 15;
    const int r = idx & 32767;
    const int j = r >> 7;        // Wcat row (0..255)
    const int k = r & 127;       // k col
    const float v = w[l * 32768 + (j & 127) * 256 + (j >> 7) * 128 + k];
    const __nv_bfloat16 hi = __float2bfloat16(v);
    const __nv_bfloat16 lo = __float2bfloat16(v - __bfloat162float(hi));
    g_wcat[l][0][j][k] = hi;
    g_wcat[l][1][j][k] = lo;
}

// ---------------- build positional row lists ----------------
// list1[b][s*11+u]: u==0 -> m_s ; u>0 -> neigh[b, m_s, u-1]
// where m_0 = 0, m_s = neigh[b, 0, s-1] (s=1..10). Stored as absolute rows b*512+node.
__global__ __launch_bounds__(128) void build_lists_kernel(const int* __restrict__ neigh) {
    const int b = blockIdx.x, t = threadIdx.x;
    if (t < S1N) {
        const int s = t / 11, u = t - s * 11;
        const int m = (s == 0) ? 0 : __ldg(neigh + (b * Nv) * Kv + (s - 1));
        const int node = (u == 0) ? m : __ldg(neigh + (b * Nv + m) * Kv + (u - 1));
        g_list1[b * S1N + t] = b * Nv + node;
    }
}

// ---------------- GEMM: Y[rows x 256] = A[rows x 128] @ Wcat^T (bf16x3 split) ----------------
__global__ __launch_bounds__(256, 1) void gemm_split(
    const float* __restrict__ Ain, const int* __restrict__ list,
    const __nv_bfloat16* __restrict__ wplanes, float* __restrict__ Y, int ntiles)
{
    extern __shared__ char sm[];
    const uint32_t smb = smem_u32(sm);
    const int t = threadIdx.x, lane = t & 31, warp = t >> 5;

    // stage both W split planes once (139264 B)
    {
        const uint4* src = (const uint4*)wplanes;
        uint4* dst = (uint4*)sm;
        #pragma unroll
        for (int i = 0; i < 34; ++i)
            dst[t + i * 256] = __ldg(src + t + i * 256);
    }

    const int wm = (warp >> 2) * 32;     // warp m: 0/32
    const int wn = (warp & 3) * 64;      // warp n: 0/64/128/192
    const int qr = lane >> 2, qc = (lane & 3) * 2;

    // ldmatrix lane addresses (A: frag order [r,c0],[r+8,c0],[r,c8],[r+8,c8])
    uint32_t aaddr[2][2], baddr[2][4];
    {
        const int ra = (lane & 7) + ((lane >> 3) & 1) * 8;
        const int ca = ((lane >> 4) & 1) * 16;
        #pragma unroll
        for (int p = 0; p < 2; ++p)
            #pragma unroll
            for (int mf = 0; mf < 2; ++mf)
                aaddr[p][mf] = smb + A_OFF + p * A_PLANE + (wm + mf * 16 + ra) * 272 + ca;
        // B: matrices [n0-7 c0],[n0-7 c8],[n8-15 c0],[n8-15 c8] per nf-pair
        const int rb = (lane & 7) + ((lane >> 4) & 1) * 8;
        const int cb = ((lane >> 3) & 1) * 16;
        #pragma unroll
        for (int p = 0; p < 2; ++p)
            #pragma unroll
            for (int nfp = 0; nfp < 4; ++nfp)
                baddr[p][nfp] = smb + p * W_PLANE + (wn + nfp * 16 + rb) * 272 + cb;
    }

    for (int tile = blockIdx.x; tile < ntiles; tile += gridDim.x) {
        // ---- stage A tile (64 rows x 128), split to hi/lo planes ----
        {
            const int r = t >> 2, c0 = (t & 3) * 32;
            const int grow = tile * 64 + r;
            const int arow = list ? __ldg(list + grow) : grow;
            const float4* src = (const float4*)(Ain + arow * 128 + c0);
            #pragma unroll
            for (int q = 0; q < 8; ++q) {
                const float4 v = __ldg(src + q);
                uint2 hi, lo;
                split4(v, hi, lo);
                char* p0 = sm + A_OFF + r * 272 + (c0 + q * 4) * 2;
                *(uint2*)p0 = hi;
                *(uint2*)(p0 + A_PLANE) = lo;
            }
        }
        __syncthreads();

        float acc[2][8][4];
        #pragma unroll
        for (int mf = 0; mf < 2; ++mf)
            #pragma unroll
            for (int nf = 0; nf < 8; ++nf)
                #pragma unroll
                for (int q = 0; q < 4; ++q) acc[mf][nf][q] = 0.f;

        #pragma unroll
        for (int ks = 0; ks < 8; ++ks) {
            const uint32_t off = ks * 32;
            uint32_t AH[2][4], AL[2][4];
            ldsm_x4(AH[0], aaddr[0][0] + off);
            ldsm_x4(AH[1], aaddr[0][1] + off);
            ldsm_x4(AL[0], aaddr[1][0] + off);
            ldsm_x4(AL[1], aaddr[1][1] + off);
            #pragma unroll
            for (int nfp = 0; nfp < 4; ++nfp) {
                uint32_t BH[4], BL[4];
                ldsm_x4(BH, baddr[0][nfp] + off);
                ldsm_x4(BL, baddr[1][nfp] + off);
                #pragma unroll
                for (int h = 0; h < 2; ++h) {
                    const int nf = nfp * 2 + h;
                    const uint32_t bh0 = BH[h * 2], bh1 = BH[h * 2 + 1];
                    const uint32_t bl0 = BL[h * 2], bl1 = BL[h * 2 + 1];
                    #pragma unroll
                    for (int mf = 0; mf < 2; ++mf) {
                        mma_bf16(acc[mf][nf], AH[mf], bh0, bh1);
                        mma_bf16(acc[mf][nf], AL[mf], bh0, bh1);
                        mma_bf16(acc[mf][nf], AH[mf], bl0, bl1);
                    }
                }
            }
        }

        // ---- store Y tile (raw, bias added later) ----
        #pragma unroll
        for (int mf = 0; mf < 2; ++mf) {
            const int r0 = tile * 64 + wm + mf * 16 + qr;
            #pragma unroll
            for (int nf = 0; nf < 8; ++nf) {
                const int col = wn + nf * 8 + qc;
                *(float2*)(Y + r0 * 256 + col) =
                    make_float2(acc[mf][nf][0], acc[mf][nf][1]);
                *(float2*)(Y + (r0 + 8) * 256 + col) =
                    make_float2(acc[mf][nf][2], acc[mf][nf][3]);
            }
        }
        __syncthreads();
    }
}

// ---------------- combine1: h1_c[b,s,:] = mean_u Y1mp + Y1self + bias ----------------
__global__ __launch_bounds__(128) void combine1_kernel(const float* __restrict__ bias) {
    const int b = blockIdx.x, f = threadIdx.x;
    const float* Yb = g_y1 + b * S1N * 256;
    const float bf = __ldg(bias + f);
    #pragma unroll
    for (int s = 0; s < S2N; ++s) {
        float a = 0.f;
        #pragma unroll
        for (int u = 1; u < 11; ++u)
            a += __ldg(Yb + (s * 11 + u) * 256 + f);
        g_h1c[(b * S2N + s) * 128 + f] =
            a * (1.0f / Kv) + __ldg(Yb + (s * 11) * 256 + 128 + f) + bf;
    }
}

// ---------------- combine2 + lin1: z[b,:] ----------------
__global__ __launch_bounds__(128) void combine_lin1_kernel(
    const float* __restrict__ bias2,
    const float* __restrict__ l1w, const float* __restrict__ l1b,
    float* __restrict__ z)
{
    __shared__ float h2[128];
    __shared__ float red[2][64];
    const int b = blockIdx.x, t = threadIdx.x;
    {
        const float* Yb = g_y2 + b * S2N * 256;
        float a = 0.f;
        #pragma unroll
        for (int s = 1; s < 11; ++s)
            a += __ldg(Yb + s * 256 + t);
        h2[t] = a * (1.0f / Kv) + __ldg(Yb + 128 + t) + __ldg(bias2 + t);
    }
    __syncthreads();
    {
        const int j = t & 63, half = t >> 6;
        const float* wr = l1w + j * 128 + half * 64;
        float s = 0.f;
        #pragma unroll
        for (int q = 0; q < 64; ++q)
            s = fmaf(h2[half * 64 + q], __ldg(wr + q), s);
        red[half][j] = s;
    }
    __syncthreads();
    if (t < 64)
        z[b * 64 + t] = red[0][t] + red[1][t] + __ldg(l1b + t);
}

// ---------------- tail: BN -> relu -> lin2 -> softmax ----------------
__global__ __launch_bounds__(128) void tail_kernel(
    const float* __restrict__ z_in,
    const float* __restrict__ gamma, const float* __restrict__ beta,
    const float* __restrict__ l2w, const float* __restrict__ l2b,
    float* __restrict__ out)
{
    __shared__ float s_z[Bv][65];
    __shared__ float s_scale[64], s_shift[64];
    const int t = threadIdx.x;

    for (int o = t; o < Bv * 64; o += 128) s_z[o >> 6][o & 63] = z_in[o];
    __syncthreads();

    if (t < 64) {
        float mu = 0.f;
        #pragma unroll 4
        for (int b = 0; b < Bv; ++b) mu += s_z[b][t];
        mu *= (1.0f / Bv);
        float var = 0.f;
        #pragma unroll 4
        for (int b = 0; b < Bv; ++b) { const float d = s_z[b][t] - mu; var += d * d; }
        var *= (1.0f / Bv);
        const float sc = gamma[t] * rsqrtf(var + 1e-5f);
        s_scale[t] = sc;
        s_shift[t] = beta[t] - mu * sc;
    }
    __syncthreads();

    for (int o = t; o < Bv * 64; o += 128) {
        const int b = o >> 6, j = o & 63;
        s_z[b][j] = fmaxf(s_z[b][j] * s_scale[j] + s_shift[j], 0.f);
    }
    __syncthreads();

    {
        float lg[Cv];
        #pragma unroll
        for (int c = 0; c < Cv; ++c) {
            const float* wr = l2w + c * 64;
            float s = 0.f;
            #pragma unroll
            for (int j = 0; j < 64; ++j) s = fmaf(s_z[t][j], wr[j], s);
            lg[c] = s + l2b[c];
        }
        float m = lg[0];
        #pragma unroll
        for (int c = 1; c < Cv; ++c) m = fmaxf(m, lg[c]);
        float sum = 0.f;
        #pragma unroll
        for (int c = 0; c < Cv; ++c) { lg[c] = expf(lg[c] - m); sum += lg[c]; }
        const float r = 1.0f / sum;
        #pragma unroll
        for (int c = 0; c < Cv; ++c) out[t * Cv + c] = lg[c] * r;
    }
}

extern "C" void kernel_launch(void* const* d_in, const int* in_sizes, int n_in,
                              void* d_out, int out_size) {
    const float* x      = (const float*)d_in[0];
    const int*   neigh  = (const int*)  d_in[1];
    const float* w_sage = (const float*)d_in[2];
    const float* b_sage = (const float*)d_in[3];
    const float* l1w    = (const float*)d_in[4];
    const float* l1b    = (const float*)d_in[5];
    const float* gamma  = (const float*)d_in[6];
    const float* beta   = (const float*)d_in[7];
    const float* l2w    = (const float*)d_in[8];
    const float* l2b    = (const float*)d_in[9];
    float* out = (float*)d_out;

    cudaFuncSetAttribute(gemm_split,
                         cudaFuncAttributeMaxDynamicSharedMemorySize, SMEM_BYTES);

    void *py1, *py2, *ph, *pl, *pw, *pz;
    cudaGetSymbolAddress(&py1, g_y1);
    cudaGetSymbolAddress(&py2, g_y2);
    cudaGetSymbolAddress(&ph,  g_h1c);
    cudaGetSymbolAddress(&pl,  g_list1);
    cudaGetSymbolAddress(&pw,  g_wcat);
    cudaGetSymbolAddress(&pz,  g_z);
    float* y1 = (float*)py1;
    float* y2 = (float*)py2;
    float* h1c = (float*)ph;
    int*   list1 = (int*)pl;
    __nv_bfloat16* wcat = (__nv_bfloat16*)pw;
    float* z = (float*)pz;

    prep_w_kernel<<<256, 256>>>(w_sage);
    build_lists_kernel<<<Bv, 128>>>(neigh);

    const int wlayer = 2 * 256 * PITCH;   // bf16 elems per layer in g_wcat
    gemm_split<<<148, 256, SMEM_BYTES>>>(x,   list1,   wcat,          y1, TILES1);
    combine1_kernel<<<Bv, 128>>>(b_sage);
    gemm_split<<<TILES2, 256, SMEM_BYTES>>>(h1c, nullptr, wcat + wlayer, y2, TILES2);
    combine_lin1_kernel<<<Bv, 128>>>(b_sage + Fv, l1w, l1b, z);
    tail_kernel<<<1, 128>>>(z, gamma, beta, l2w, l2b, out);
}

// round 7
// speedup vs baseline: 3.5048x; 1.3541x over previous
#include <cuda_runtime.h>
#include <cuda_bf16.h>
#include <math.h>
#include <stdint.h>

// Problem constants
constexpr int Bv = 128, Nv = 512, Kv = 10, Fv = 128, TFv = 256, Cv = 40;

// Cone: per batch, layer-2 needs h1 at {0} U neigh[b,0] = 11 nodes
constexpr int S2N   = 11;
constexpr int NR1   = Bv * S2N;      // 1408 GEMM1 rows
constexpr int TILES1 = NR1 / 64;     // 22

// GEMM1 smem (bytes): W [128n x 264k] bf16 x2 parts, A [64 x 264] x2 parts
constexpr int WPITCH  = 264;
constexpr int W_PLANE = 128 * WPITCH * 2;   // 67584
constexpr int A_OFF   = 2 * W_PLANE;        // 135168
constexpr int A_PLANE = 64 * WPITCH * 2;    // 33792
constexpr int SMEM_BYTES = A_OFF + 2 * A_PLANE;  // 202752

// Scratch (static device globals: allocation-free rule)
__device__ float g_h1c[NR1 * 128];            // h1 at cone nodes
__device__ float g_z[Bv * 64];
// Split layer-0 weights: [part hi/lo][128 out][WPITCH k] (k = [mp(128), self(128)])
__device__ __align__(16) __nv_bfloat16 g_w0[2][128][WPITCH];

// ---------------- HMMA / LDSM helpers ----------------
__device__ __forceinline__ void mma_bf16(float* c, const uint32_t* a,
                                         uint32_t b0, uint32_t b1) {
    asm volatile(
        "mma.sync.aligned.m16n8k16.row.col.f32.bf16.bf16.f32 "
        "{%0,%1,%2,%3}, {%4,%5,%6,%7}, {%8,%9}, {%0,%1,%2,%3};"
        : "+f"(c[0]), "+f"(c[1]), "+f"(c[2]), "+f"(c[3])
        : "r"(a[0]), "r"(a[1]), "r"(a[2]), "r"(a[3]), "r"(b0), "r"(b1));
}
__device__ __forceinline__ void ldsm_x4(uint32_t* r, uint32_t addr) {
    asm volatile("ldmatrix.sync.aligned.m8n8.x4.shared.b16 {%0,%1,%2,%3}, [%4];"
                 : "=r"(r[0]), "=r"(r[1]), "=r"(r[2]), "=r"(r[3]) : "r"(addr));
}
__device__ __forceinline__ uint32_t smem_u32(const void* p) {
    uint32_t a;
    asm("{ .reg .u64 t; cvta.to.shared.u64 t, %1; cvt.u32.u64 %0, t; }"
        : "=r"(a) : "l"(p));
    return a;
}
__device__ __forceinline__ void split4(const float4 v, uint2& hi, uint2& lo) {
    __nv_bfloat16 h[4], l[4];
    const float va[4] = {v.x, v.y, v.z, v.w};
    #pragma unroll
    for (int q = 0; q < 4; ++q) {
        h[q] = __float2bfloat16(va[q]);
        l[q] = __float2bfloat16(va[q] - __bfloat162float(h[q]));
    }
    hi = *(uint2*)h;
    lo = *(uint2*)l;
}

// ---------------- prep: split layer-0 W into bf16 hi/lo, pitch 264 ----------------
__global__ __launch_bounds__(256) void prep_w_kernel(const float* __restrict__ w) {
    const int idx = blockIdx.x * 256 + threadIdx.x;   // 128*256 = 32768
    const int n = idx >> 8;       // out row (0..127)
    const int k = idx & 255;      // k col (cat dim)
    const float v = w[n * 256 + k];
    const __nv_bfloat16 hi = __float2bfloat16(v);
    g_w0[0][n][k] = hi;
    g_w0[1][n][k] = __float2bfloat16(v - __bfloat162float(hi));
}

// ---------------- GEMM1 (fused gather-mean): h1c = [mp,self] @ W0^T + b0 ----------------
// 22 CTAs x 256 threads; rows = b*11+s; m_0=0, m_s=neigh[b,0,s-1]
__global__ __launch_bounds__(256, 1) void gemm1_kernel(
    const float* __restrict__ x, const int* __restrict__ neigh,
    const float* __restrict__ bias)
{
    extern __shared__ char sm[];
    const uint32_t smb = smem_u32(sm);
    const int t = threadIdx.x, lane = t & 31, warp = t >> 5;
    const int tile = blockIdx.x;

    // ---- stage W planes (135168 B contiguous) ----
    {
        const uint4* src = (const uint4*)&g_w0[0][0][0];
        uint4* dst = (uint4*)sm;
        #pragma unroll
        for (int i = 0; i < 33; ++i)          // 33*256 = 8448 uint4
            dst[t + i * 256] = __ldg(src + t + i * 256);
    }

    // ---- gather-mean + self into A planes ----
    for (int r = warp * 8; r < warp * 8 + 8; ++r) {
        const int grow = tile * 64 + r;       // 0..1407
        const int b = grow / 11;
        const int s = grow - b * 11;
        const int m = (s == 0) ? 0 : __ldg(neigh + (b * Nv) * Kv + (s - 1));
        const int* nb = neigh + (b * Nv + m) * Kv;
        float4 a4 = make_float4(0.f, 0.f, 0.f, 0.f);
        #pragma unroll
        for (int k = 0; k < Kv; ++k) {
            const int idx = __ldg(nb + k);
            const float4 v = __ldg((const float4*)(x + (b * Nv + idx) * Fv) + lane);
            a4.x += v.x; a4.y += v.y; a4.z += v.z; a4.w += v.w;
        }
        const float inv = 1.0f / Kv;
        a4 = make_float4(a4.x * inv, a4.y * inv, a4.z * inv, a4.w * inv);
        uint2 hi, lo;
        split4(a4, hi, lo);
        char* p0 = sm + A_OFF + r * 528 + lane * 8;
        *(uint2*)p0 = hi;
        *(uint2*)(p0 + A_PLANE) = lo;
        const float4 hv = __ldg((const float4*)(x + (b * Nv + m) * Fv) + lane);
        split4(hv, hi, lo);
        *(uint2*)(p0 + 256) = hi;              // col 128 start
        *(uint2*)(p0 + 256 + A_PLANE) = lo;
    }
    __syncthreads();

    // ---- MMA: 64m x 128n, K=256; warps 2m x 4n of 32x32 ----
    const int wm = (warp >> 2) * 32;
    const int wn = (warp & 3) * 32;
    const int qr = lane >> 2, qc = (lane & 3) * 2;

    uint32_t aaddr[2][2], baddr[2][2];
    {
        const int ra = (lane & 7) + ((lane >> 3) & 1) * 8;
        const int ca = ((lane >> 4) & 1) * 16;
        #pragma unroll
        for (int p = 0; p < 2; ++p)
            #pragma unroll
            for (int mf = 0; mf < 2; ++mf)
                aaddr[p][mf] = smb + A_OFF + p * A_PLANE + (wm + mf * 16 + ra) * 528 + ca;
        const int rb = (lane & 7) + ((lane >> 4) & 1) * 8;
        const int cb = ((lane >> 3) & 1) * 16;
        #pragma unroll
        for (int p = 0; p < 2; ++p)
            #pragma unroll
            for (int nfp = 0; nfp < 2; ++nfp)
                baddr[p][nfp] = smb + p * W_PLANE + (wn + nfp * 16 + rb) * 528 + cb;
    }

    float acc[2][4][4];
    #pragma unroll
    for (int mf = 0; mf < 2; ++mf)
        #pragma unroll
        for (int nf = 0; nf < 4; ++nf)
            #pragma unroll
            for (int q = 0; q < 4; ++q) acc[mf][nf][q] = 0.f;

    #pragma unroll
    for (int ks = 0; ks < 16; ++ks) {
        const uint32_t off = ks * 32;
        uint32_t AH[2][4], AL[2][4];
        ldsm_x4(AH[0], aaddr[0][0] + off);
        ldsm_x4(AH[1], aaddr[0][1] + off);
        ldsm_x4(AL[0], aaddr[1][0] + off);
        ldsm_x4(AL[1], aaddr[1][1] + off);
        #pragma unroll
        for (int nfp = 0; nfp < 2; ++nfp) {
            uint32_t BH[4], BL[4];
            ldsm_x4(BH, baddr[0][nfp] + off);
            ldsm_x4(BL, baddr[1][nfp] + off);
            #pragma unroll
            for (int h = 0; h < 2; ++h) {
                const int nf = nfp * 2 + h;
                const uint32_t bh0 = BH[h * 2], bh1 = BH[h * 2 + 1];
                const uint32_t bl0 = BL[h * 2], bl1 = BL[h * 2 + 1];
                #pragma unroll
                for (int mf = 0; mf < 2; ++mf) {
                    mma_bf16(acc[mf][nf], AH[mf], bh0, bh1);
                    mma_bf16(acc[mf][nf], AL[mf], bh0, bh1);
                    mma_bf16(acc[mf][nf], AH[mf], bl0, bl1);
                }
            }
        }
    }

    // ---- epilogue: + bias, store h1c ----
    #pragma unroll
    for (int mf = 0; mf < 2; ++mf) {
        const int r0 = tile * 64 + wm + mf * 16 + qr;
        #pragma unroll
        for (int nf = 0; nf < 4; ++nf) {
            const int col = wn + nf * 8 + qc;
            const float b0 = __ldg(bias + col);
            const float b1 = __ldg(bias + col + 1);
            *(float2*)(g_h1c + r0 * 128 + col) =
                make_float2(acc[mf][nf][0] + b0, acc[mf][nf][1] + b1);
            *(float2*)(g_h1c + (r0 + 8) * 128 + col) =
                make_float2(acc[mf][nf][2] + b0, acc[mf][nf][3] + b1);
        }
    }
}

// ---------------- stage2 + layer-2 GEMM (fp32) + lin1, one block per b ----------------
__global__ __launch_bounds__(128) void stage2_kernel(
    const float* __restrict__ w_sage, const float* __restrict__ b_sage,
    const float* __restrict__ l1w, const float* __restrict__ l1b,
    float* __restrict__ z)
{
    __shared__ float a2[256];
    __shared__ float h2s[128];
    __shared__ float red[2][64];
    const int b = blockIdx.x, t = threadIdx.x;

    // a2 = [mean_{s=1..10} h1c[b,s], h1c[b,0]]
    {
        const float* hb = g_h1c + b * S2N * 128;
        float a = 0.f;
        #pragma unroll
        for (int s = 1; s < 11; ++s) a += __ldg(hb + s * 128 + t);
        a2[t] = a * (1.0f / Kv);
        a2[128 + t] = __ldg(hb + t);
    }
    __syncthreads();

    // h2[t] = a2 . W1[t,:] + b1[t]   (fp32 exact)
    {
        const float4* wr = (const float4*)(w_sage + 32768 + t * 256);
        const float4* ar = (const float4*)a2;
        float s = 0.f;
        #pragma unroll
        for (int q = 0; q < 64; ++q) {
            const float4 w = __ldg(wr + q);
            const float4 a = ar[q];
            s = fmaf(a.x, w.x, s); s = fmaf(a.y, w.y, s);
            s = fmaf(a.z, w.z, s); s = fmaf(a.w, w.w, s);
        }
        h2s[t] = s + __ldg(b_sage + 128 + t);
    }
    __syncthreads();

    // z[b,j] = h2 . l1w[j,:] + l1b[j]  (two half-dots per j)
    {
        const int j = t & 63, half = t >> 6;
        const float4* wr = (const float4*)(l1w + j * 128) + half * 16;
        const float4* hr = (const float4*)h2s + half * 16;
        float s = 0.f;
        #pragma unroll
        for (int q = 0; q < 16; ++q) {
            const float4 w = __ldg(wr + q);
            const float4 a = hr[q];
            s = fmaf(a.x, w.x, s); s = fmaf(a.y, w.y, s);
            s = fmaf(a.z, w.z, s); s = fmaf(a.w, w.w, s);
        }
        red[half][j] = s;
    }
    __syncthreads();
    if (t < 64)
        z[b * 64 + t] = red[0][t] + red[1][t] + __ldg(l1b + t);
}

// ---------------- tail: BN -> relu -> lin2 -> softmax ----------------
__global__ __launch_bounds__(128) void tail_kernel(
    const float* __restrict__ z_in,
    const float* __restrict__ gamma, const float* __restrict__ beta,
    const float* __restrict__ l2w, const float* __restrict__ l2b,
    float* __restrict__ out)
{
    __shared__ float s_z[Bv][65];
    __shared__ float s_scale[64], s_shift[64];
    const int t = threadIdx.x;

    for (int o = t; o < Bv * 64; o += 128) s_z[o >> 6][o & 63] = z_in[o];
    __syncthreads();

    if (t < 64) {
        float mu = 0.f;
        #pragma unroll 4
        for (int b = 0; b < Bv; ++b) mu += s_z[b][t];
        mu *= (1.0f / Bv);
        float var = 0.f;
        #pragma unroll 4
        for (int b = 0; b < Bv; ++b) { const float d = s_z[b][t] - mu; var += d * d; }
        var *= (1.0f / Bv);
        const float sc = gamma[t] * rsqrtf(var + 1e-5f);
        s_scale[t] = sc;
        s_shift[t] = beta[t] - mu * sc;
    }
    __syncthreads();

    for (int o = t; o < Bv * 64; o += 128) {
        const int b = o >> 6, j = o & 63;
        s_z[b][j] = fmaxf(s_z[b][j] * s_scale[j] + s_shift[j], 0.f);
    }
    __syncthreads();

    {
        float lg[Cv];
        #pragma unroll
        for (int c = 0; c < Cv; ++c) {
            const float* wr = l2w + c * 64;
            float s = 0.f;
            #pragma unroll
            for (int j = 0; j < 64; ++j) s = fmaf(s_z[t][j], wr[j], s);
            lg[c] = s + l2b[c];
        }
        float m = lg[0];
        #pragma unroll
        for (int c = 1; c < Cv; ++c) m = fmaxf(m, lg[c]);
        float sum = 0.f;
        #pragma unroll
        for (int c = 0; c < Cv; ++c) { lg[c] = expf(lg[c] - m); sum += lg[c]; }
        const float r = 1.0f / sum;
        #pragma unroll
        for (int c = 0; c < Cv; ++c) out[t * Cv + c] = lg[c] * r;
    }
}

extern "C" void kernel_launch(void* const* d_in, const int* in_sizes, int n_in,
                              void* d_out, int out_size) {
    const float* x      = (const float*)d_in[0];
    const int*   neigh  = (const int*)  d_in[1];
    const float* w_sage = (const float*)d_in[2];
    const float* b_sage = (const float*)d_in[3];
    const float* l1w    = (const float*)d_in[4];
    const float* l1b    = (const float*)d_in[5];
    const float* gamma  = (const float*)d_in[6];
    const float* beta   = (const float*)d_in[7];
    const float* l2w    = (const float*)d_in[8];
    const float* l2b    = (const float*)d_in[9];
    float* out = (float*)d_out;

    cudaFuncSetAttribute(gemm1_kernel,
                         cudaFuncAttributeMaxDynamicSharedMemorySize, SMEM_BYTES);

    void* pz;
    cudaGetSymbolAddress(&pz, g_z);
    float* z = (float*)pz;

    prep_w_kernel<<<128, 256>>>(w_sage);
    gemm1_kernel<<<TILES1, 256, SMEM_BYTES>>>(x, neigh, b_sage);
    stage2_kernel<<<Bv, 128>>>(w_sage, b_sage, l1w, l1b, z);
    tail_kernel<<<1, 128>>>(z, gamma, beta, l2w, l2b, out);
}

// round 9
// speedup vs baseline: 5.2538x; 1.4990x over previous
#include <cuda_runtime.h>
#include <cuda_bf16.h>
#include <math.h>
#include <stdint.h>

// Problem constants
constexpr int Bv = 128, Nv = 512, Kv = 10, Fv = 128, TFv = 256, Cv = 40;

// Cone: per batch, layer-2 needs h1 at {0} U neigh[b,0] = 11 nodes
constexpr int S2N   = 11;
constexpr int NR1   = Bv * S2N;      // 1408 GEMM1 rows
constexpr int TILES1 = NR1 / 64;     // 22

// GEMM1 smem (bytes): W [128n x 264k] bf16 x2 parts, A [64 x 264] x2 parts
constexpr int WPITCH  = 264;
constexpr int W_PLANE = 128 * WPITCH * 2;   // 67584
constexpr int A_OFF   = 2 * W_PLANE;        // 135168
constexpr int A_PLANE = 64 * WPITCH * 2;    // 33792
constexpr int SMEM_BYTES = A_OFF + 2 * A_PLANE;  // 202752

// Scratch (static device globals: allocation-free rule)
__device__ float g_h1c[NR1 * 128];            // h1 at cone nodes
__device__ float g_z[Bv * 64];

// ---------------- HMMA / LDSM helpers ----------------
__device__ __forceinline__ void mma_bf16(float* c, const uint32_t* a,
                                         uint32_t b0, uint32_t b1) {
    asm volatile(
        "mma.sync.aligned.m16n8k16.row.col.f32.bf16.bf16.f32 "
        "{%0,%1,%2,%3}, {%4,%5,%6,%7}, {%8,%9}, {%0,%1,%2,%3};"
        : "+f"(c[0]), "+f"(c[1]), "+f"(c[2]), "+f"(c[3])
        : "r"(a[0]), "r"(a[1]), "r"(a[2]), "r"(a[3]), "r"(b0), "r"(b1));
}
__device__ __forceinline__ void ldsm_x4(uint32_t* r, uint32_t addr) {
    asm volatile("ldmatrix.sync.aligned.m8n8.x4.shared.b16 {%0,%1,%2,%3}, [%4];"
                 : "=r"(r[0]), "=r"(r[1]), "=r"(r[2]), "=r"(r[3]) : "r"(addr));
}
__device__ __forceinline__ uint32_t smem_u32(const void* p) {
    uint32_t a;
    asm("{ .reg .u64 t; cvta.to.shared.u64 t, %1; cvt.u32.u64 %0, t; }"
        : "=r"(a) : "l"(p));
    return a;
}
__device__ __forceinline__ void split4(const float4 v, uint2& hi, uint2& lo) {
    __nv_bfloat16 h[4], l[4];
    const float va[4] = {v.x, v.y, v.z, v.w};
    #pragma unroll
    for (int q = 0; q < 4; ++q) {
        h[q] = __float2bfloat16(va[q]);
        l[q] = __float2bfloat16(va[q] - __bfloat162float(h[q]));
    }
    hi = *(uint2*)h;
    lo = *(uint2*)l;
}

// ---------------- GEMM1 (fused gather-mean + inline W split) ----------------
// h1c[row] = [mp(row), self(row)] @ W0^T + b0 ; rows = b*11+s
__global__ __launch_bounds__(256, 1) void gemm1_kernel(
    const float* __restrict__ x, const int* __restrict__ neigh,
    const float* __restrict__ w0, const float* __restrict__ bias)
{
    extern __shared__ char sm[];
    const uint32_t smb = smem_u32(sm);
    const int t = threadIdx.x, lane = t & 31, warp = t >> 5;
    const int tile = blockIdx.x;

    // ---- stage + split W0 (fp32 -> bf16 hi/lo planes), coalesced ----
    {
        const float4* src = (const float4*)w0;    // 8192 float4
        #pragma unroll
        for (int i = 0; i < 32; ++i) {
            const int idx4 = t + i * 256;
            const float4 v = __ldg(src + idx4);
            const int n  = idx4 >> 6;             // 64 float4 per 256-col row
            const int k4 = (idx4 & 63) * 4;
            uint2 hi, lo;
            split4(v, hi, lo);
            char* p = sm + n * 528 + k4 * 2;
            *(uint2*)p = hi;
            *(uint2*)(p + W_PLANE) = lo;
        }
    }

    // ---- gather-mean + self into A planes ----
    for (int r = warp * 8; r < warp * 8 + 8; ++r) {
        const int grow = tile * 64 + r;           // 0..1407
        const int b = grow / 11;
        const int s = grow - b * 11;
        const int m = (s == 0) ? 0 : __ldg(neigh + (b * Nv) * Kv + (s - 1));
        const int* nb = neigh + (b * Nv + m) * Kv;
        float4 a4 = make_float4(0.f, 0.f, 0.f, 0.f);
        #pragma unroll
        for (int k = 0; k < Kv; ++k) {
            const int idx = __ldg(nb + k);
            const float4 v = __ldg((const float4*)(x + (b * Nv + idx) * Fv) + lane);
            a4.x += v.x; a4.y += v.y; a4.z += v.z; a4.w += v.w;
        }
        const float inv = 1.0f / Kv;
        a4 = make_float4(a4.x * inv, a4.y * inv, a4.z * inv, a4.w * inv);
        uint2 hi, lo;
        split4(a4, hi, lo);
        char* p0 = sm + A_OFF + r * 528 + lane * 8;
        *(uint2*)p0 = hi;
        *(uint2*)(p0 + A_PLANE) = lo;
        const float4 hv = __ldg((const float4*)(x + (b * Nv + m) * Fv) + lane);
        split4(hv, hi, lo);
        *(uint2*)(p0 + 256) = hi;                 // col 128 start
        *(uint2*)(p0 + 256 + A_PLANE) = lo;
    }
    __syncthreads();

    // ---- MMA: 64m x 128n, K=256; warps 2m x 4n of 32x32 ----
    const int wm = (warp >> 2) * 32;
    const int wn = (warp & 3) * 32;
    const int qr = lane >> 2, qc = (lane & 3) * 2;

    uint32_t aaddr[2][2], baddr[2][2];
    {
        const int ra = (lane & 7) + ((lane >> 3) & 1) * 8;
        const int ca = ((lane >> 4) & 1) * 16;
        #pragma unroll
        for (int p = 0; p < 2; ++p)
            #pragma unroll
            for (int mf = 0; mf < 2; ++mf)
                aaddr[p][mf] = smb + A_OFF + p * A_PLANE + (wm + mf * 16 + ra) * 528 + ca;
        const int rb = (lane & 7) + ((lane >> 4) & 1) * 8;
        const int cb = ((lane >> 3) & 1) * 16;
        #pragma unroll
        for (int p = 0; p < 2; ++p)
            #pragma unroll
            for (int nfp = 0; nfp < 2; ++nfp)
                baddr[p][nfp] = smb + p * W_PLANE + (wn + nfp * 16 + rb) * 528 + cb;
    }

    float acc[2][4][4];
    #pragma unroll
    for (int mf = 0; mf < 2; ++mf)
        #pragma unroll
        for (int nf = 0; nf < 4; ++nf)
            #pragma unroll
            for (int q = 0; q < 4; ++q) acc[mf][nf][q] = 0.f;

    #pragma unroll
    for (int ks = 0; ks < 16; ++ks) {
        const uint32_t off = ks * 32;
        uint32_t AH[2][4], AL[2][4];
        ldsm_x4(AH[0], aaddr[0][0] + off);
        ldsm_x4(AH[1], aaddr[0][1] + off);
        ldsm_x4(AL[0], aaddr[1][0] + off);
        ldsm_x4(AL[1], aaddr[1][1] + off);
        #pragma unroll
        for (int nfp = 0; nfp < 2; ++nfp) {
            uint32_t BH[4], BL[4];
            ldsm_x4(BH, baddr[0][nfp] + off);
            ldsm_x4(BL, baddr[1][nfp] + off);
            #pragma unroll
            for (int h = 0; h < 2; ++h) {
                const int nf = nfp * 2 + h;
                const uint32_t bh0 = BH[h * 2], bh1 = BH[h * 2 + 1];
                const uint32_t bl0 = BL[h * 2], bl1 = BL[h * 2 + 1];
                #pragma unroll
                for (int mf = 0; mf < 2; ++mf) {
                    mma_bf16(acc[mf][nf], AH[mf], bh0, bh1);
                    mma_bf16(acc[mf][nf], AL[mf], bh0, bh1);
                    mma_bf16(acc[mf][nf], AH[mf], bl0, bl1);
                }
            }
        }
    }

    // ---- epilogue: + bias, store h1c ----
    #pragma unroll
    for (int mf = 0; mf < 2; ++mf) {
        const int r0 = tile * 64 + wm + mf * 16 + qr;
        #pragma unroll
        for (int nf = 0; nf < 4; ++nf) {
            const int col = wn + nf * 8 + qc;
            const float b0 = __ldg(bias + col);
            const float b1 = __ldg(bias + col + 1);
            *(float2*)(g_h1c + r0 * 128 + col) =
                make_float2(acc[mf][nf][0] + b0, acc[mf][nf][1] + b1);
            *(float2*)(g_h1c + (r0 + 8) * 128 + col) =
                make_float2(acc[mf][nf][2] + b0, acc[mf][nf][3] + b1);
        }
    }
}

// ---------------- stage2 + layer-2 GEMM (fp32) + lin1, one block per b ----------------
__global__ __launch_bounds__(128) void stage2_kernel(
    const float* __restrict__ w_sage, const float* __restrict__ b_sage,
    const float* __restrict__ l1w, const float* __restrict__ l1b,
    float* __restrict__ z)
{
    __shared__ float a2[256];
    __shared__ float h2s[128];
    __shared__ float red[2][64];
    const int b = blockIdx.x, t = threadIdx.x;

    // a2 = [mean_{s=1..10} h1c[b,s], h1c[b,0]]
    {
        const float* hb = g_h1c + b * S2N * 128;
        float a = 0.f;
        #pragma unroll
        for (int s = 1; s < 11; ++s) a += __ldg(hb + s * 128 + t);
        a2[t] = a * (1.0f / Kv);
        a2[128 + t] = __ldg(hb + t);
    }
    __syncthreads();

    // h2[t] = a2 . W1[t,:] + b1[t]   (fp32 exact)
    {
        const float4* wr = (const float4*)(w_sage + 32768 + t * 256);
        const float4* ar = (const float4*)a2;
        float s = 0.f;
        #pragma unroll
        for (int q = 0; q < 64; ++q) {
            const float4 w = __ldg(wr + q);
            const float4 a = ar[q];
            s = fmaf(a.x, w.x, s); s = fmaf(a.y, w.y, s);
            s = fmaf(a.z, w.z, s); s = fmaf(a.w, w.w, s);
        }
        h2s[t] = s + __ldg(b_sage + 128 + t);
    }
    __syncthreads();

    // z[b,j] = h2 . l1w[j,:] + l1b[j]  (two half-dots per j)
    {
        const int j = t & 63, half = t >> 6;
        const float4* wr = (const float4*)(l1w + j * 128) + half * 16;
        const float4* hr = (const float4*)h2s + half * 16;
        float s = 0.f;
        #pragma unroll
        for (int q = 0; q < 16; ++q) {
            const float4 w = __ldg(wr + q);
            const float4 a = hr[q];
            s = fmaf(a.x, w.x, s); s = fmaf(a.y, w.y, s);
            s = fmaf(a.z, w.z, s); s = fmaf(a.w, w.w, s);
        }
        red[half][j] = s;
    }
    __syncthreads();
    if (t < 64)
        z[b * 64 + t] = red[0][t] + red[1][t] + __ldg(l1b + t);
}

// ---------------- tail: BN -> relu -> lin2 -> softmax (1 block x 1024 threads) ----------------
__global__ __launch_bounds__(1024) void tail_kernel(
    const float* __restrict__ z_in,
    const float* __restrict__ gamma, const float* __restrict__ beta,
    const float* __restrict__ l2w, const float* __restrict__ l2b,
    float* __restrict__ out)
{
    __shared__ float s_z[Bv][65];          // pitch 65: conflict-free across b
    __shared__ float s_w[64][40];          // l2w transposed [j][c]
    __shared__ float s_ps[8][64];          // partial sums
    __shared__ float s_pq[8][64];          // partial sumsq
    __shared__ float s_scale[64], s_shift[64];
    __shared__ float s_b2[Cv];
    const int t = threadIdx.x;

    // load z (coalesced) + stage l2w transposed + l2b
    #pragma unroll
    for (int i = 0; i < 8; ++i) {
        const int o = t + i * 1024;
        s_z[o >> 6][o & 63] = __ldg(z_in + o);
    }
    for (int o = t; o < Cv * 64; o += 1024) {   // FIX: full 2560-entry staging
        const int c = o >> 6, j = o & 63;
        s_w[j][c] = __ldg(l2w + o);
    }
    if (t < Cv) s_b2[t] = __ldg(l2b + t);
    __syncthreads();

    // BN stats: 8 segments x 64 columns, then reduce
    if (t < 512) {
        const int col = t & 63, seg = t >> 6;
        float s = 0.f, q = 0.f;
        #pragma unroll
        for (int r = 0; r < 16; ++r) {
            const float v = s_z[seg * 16 + r][col];
            s += v; q = fmaf(v, v, q);
        }
        s_ps[seg][col] = s;
        s_pq[seg][col] = q;
    }
    __syncthreads();
    if (t < 64) {
        float s = 0.f, q = 0.f;
        #pragma unroll
        for (int g = 0; g < 8; ++g) { s += s_ps[g][t]; q += s_pq[g][t]; }
        const float mu  = s * (1.0f / Bv);
        const float var = q * (1.0f / Bv) - mu * mu;
        const float sc  = __ldg(gamma + t) * rsqrtf(var + 1e-5f);
        s_scale[t] = sc;
        s_shift[t] = __ldg(beta + t) - mu * sc;
    }
    __syncthreads();

    // normalize + relu in place
    #pragma unroll
    for (int i = 0; i < 8; ++i) {
        const int o = t + i * 1024;
        const int b = o >> 6, j = o & 63;
        s_z[b][j] = fmaxf(s_z[b][j] * s_scale[j] + s_shift[j], 0.f);
    }
    __syncthreads();

    // lin2 + softmax: one thread per batch row
    if (t < Bv) {
        float lg[Cv];
        #pragma unroll
        for (int c = 0; c < Cv; ++c) lg[c] = s_b2[c];
        #pragma unroll 4
        for (int j = 0; j < 64; ++j) {
            const float zj = s_z[t][j];
            #pragma unroll
            for (int c4 = 0; c4 < Cv / 4; ++c4) {
                const float4 w4 = *(const float4*)&s_w[j][c4 * 4];
                lg[c4 * 4 + 0] = fmaf(zj, w4.x, lg[c4 * 4 + 0]);
                lg[c4 * 4 + 1] = fmaf(zj, w4.y, lg[c4 * 4 + 1]);
                lg[c4 * 4 + 2] = fmaf(zj, w4.z, lg[c4 * 4 + 2]);
                lg[c4 * 4 + 3] = fmaf(zj, w4.w, lg[c4 * 4 + 3]);
            }
        }
        float m = lg[0];
        #pragma unroll
        for (int c = 1; c < Cv; ++c) m = fmaxf(m, lg[c]);
        float sum = 0.f;
        #pragma unroll
        for (int c = 0; c < Cv; ++c) { lg[c] = expf(lg[c] - m); sum += lg[c]; }
        const float r = 1.0f / sum;
        #pragma unroll
        for (int c = 0; c < Cv; ++c) out[t * Cv + c] = lg[c] * r;
    }
}

extern "C" void kernel_launch(void* const* d_in, const int* in_sizes, int n_in,
                              void* d_out, int out_size) {
    const float* x      = (const float*)d_in[0];
    const int*   neigh  = (const int*)  d_in[1];
    const float* w_sage = (const float*)d_in[2];
    const float* b_sage = (const float*)d_in[3];
    const float* l1w    = (const float*)d_in[4];
    const float* l1b    = (const float*)d_in[5];
    const float* gamma  = (const float*)d_in[6];
    const float* beta   = (const float*)d_in[7];
    const float* l2w    = (const float*)d_in[8];
    const float* l2b    = (const float*)d_in[9];
    float* out = (float*)d_out;

    cudaFuncSetAttribute(gemm1_kernel,
                         cudaFuncAttributeMaxDynamicSharedMemorySize, SMEM_BYTES);

    void* pz;
    cudaGetSymbolAddress(&pz, g_z);
    float* z = (float*)pz;

    gemm1_kernel<<<TILES1, 256, SMEM_BYTES>>>(x, neigh, w_sage, b_sage);
    stage2_kernel<<<Bv, 128>>>(w_sage, b_sage, l1w, l1b, z);
    tail_kernel<<<1, 1024>>>(z, gamma, beta, l2w, l2b, out);
}

// round 10
// speedup vs baseline: 6.8903x; 1.3115x over previous
#include <cuda_runtime.h>
#include <cuda_bf16.h>
#include <math.h>
#include <stdint.h>

// Problem constants
constexpr int Bv = 128, Nv = 512, Kv = 10, Fv = 128, TFv = 256, Cv = 40;
constexpr int S2N = 11;     // cone nodes per b: {0} U neigh[b,0]

// Fused kernel smem (bytes)
constexpr int WPITCH  = 264;                 // bf16/row (528 B, LDSM conflict-free)
constexpr int W_PLANE = 128 * WPITCH * 2;    // 67584 (one split part of W0)
constexpr int A_OFF   = 2 * W_PLANE;         // 135168
constexpr int A_PLANE = 16 * WPITCH * 2;     // 8448  (16 padded rows)
constexpr int H1_OFF  = A_OFF + 2 * A_PLANE; // 152064
constexpr int SMEM_BYTES = H1_OFF + S2N * 128 * 4;  // 157696

// Scratch (static device globals: allocation-free rule)
__device__ float g_z[Bv * 64];

// ---------------- HMMA / LDSM helpers ----------------
__device__ __forceinline__ void mma_bf16(float* c, const uint32_t* a,
                                         uint32_t b0, uint32_t b1) {
    asm volatile(
        "mma.sync.aligned.m16n8k16.row.col.f32.bf16.bf16.f32 "
        "{%0,%1,%2,%3}, {%4,%5,%6,%7}, {%8,%9}, {%0,%1,%2,%3};"
        : "+f"(c[0]), "+f"(c[1]), "+f"(c[2]), "+f"(c[3])
        : "r"(a[0]), "r"(a[1]), "r"(a[2]), "r"(a[3]), "r"(b0), "r"(b1));
}
__device__ __forceinline__ void ldsm_x4(uint32_t* r, uint32_t addr) {
    asm volatile("ldmatrix.sync.aligned.m8n8.x4.shared.b16 {%0,%1,%2,%3}, [%4];"
                 : "=r"(r[0]), "=r"(r[1]), "=r"(r[2]), "=r"(r[3]) : "r"(addr));
}
__device__ __forceinline__ uint32_t smem_u32(const void* p) {
    uint32_t a;
    asm("{ .reg .u64 t; cvta.to.shared.u64 t, %1; cvt.u32.u64 %0, t; }"
        : "=r"(a) : "l"(p));
    return a;
}
__device__ __forceinline__ void split4(const float4 v, uint2& hi, uint2& lo) {
    __nv_bfloat16 h[4], l[4];
    const float va[4] = {v.x, v.y, v.z, v.w};
    #pragma unroll
    for (int q = 0; q < 4; ++q) {
        h[q] = __float2bfloat16(va[q]);
        l[q] = __float2bfloat16(va[q] - __bfloat162float(h[q]));
    }
    hi = *(uint2*)h;
    lo = *(uint2*)l;
}

// ---------------- fused kernel: one CTA per batch element b ----------------
// layer1 (bf16x3 HMMA on 11-row cone) -> layer2 (fp32) -> lin1 -> z
__global__ __launch_bounds__(256, 1) void fused_kernel(
    const float* __restrict__ x, const int* __restrict__ neigh,
    const float* __restrict__ w_sage, const float* __restrict__ b_sage,
    const float* __restrict__ l1w, const float* __restrict__ l1b,
    float* __restrict__ z)
{
    extern __shared__ char sm[];
    __shared__ float a2[256];
    __shared__ float h2s[128];
    __shared__ float red2[2][128];
    __shared__ float red4[4][64];
    const uint32_t smb = smem_u32(sm);
    const int t = threadIdx.x, lane = t & 31, warp = t >> 5;
    const int b = blockIdx.x;

    // ---- stage + split W0 (fp32 -> bf16 hi/lo planes), coalesced ----
    {
        const float4* src = (const float4*)w_sage;   // layer 0: 8192 float4
        #pragma unroll
        for (int i = 0; i < 32; ++i) {
            const int idx4 = t + i * 256;
            const float4 v = __ldg(src + idx4);
            const int n  = idx4 >> 6;
            const int k4 = (idx4 & 63) * 4;
            uint2 hi, lo;
            split4(v, hi, lo);
            char* p = sm + n * 528 + k4 * 2;
            *(uint2*)p = hi;
            *(uint2*)(p + W_PLANE) = lo;
        }
    }

    // ---- zero padded A rows 11..15 (both planes) ----
    {
        const uint4 zz = make_uint4(0, 0, 0, 0);
        for (int o = t; o < 330; o += 256) {
            const int p = o / 165, i = o - p * 165;
            *(uint4*)(sm + A_OFF + p * A_PLANE + 11 * 528 + i * 16) = zz;
        }
    }

    // ---- gather-mean + self into A planes (11 cone rows) ----
    for (int r = warp; r < S2N; r += 8) {
        const int m = (r == 0) ? 0 : __ldg(neigh + (b * Nv) * Kv + (r - 1));
        const int* nb = neigh + (b * Nv + m) * Kv;
        float4 a4 = make_float4(0.f, 0.f, 0.f, 0.f);
        #pragma unroll
        for (int k = 0; k < Kv; ++k) {
            const int idx = __ldg(nb + k);
            const float4 v = __ldg((const float4*)(x + (b * Nv + idx) * Fv) + lane);
            a4.x += v.x; a4.y += v.y; a4.z += v.z; a4.w += v.w;
        }
        const float inv = 1.0f / Kv;
        a4 = make_float4(a4.x * inv, a4.y * inv, a4.z * inv, a4.w * inv);
        uint2 hi, lo;
        split4(a4, hi, lo);
        char* p0 = sm + A_OFF + r * 528 + lane * 8;
        *(uint2*)p0 = hi;
        *(uint2*)(p0 + A_PLANE) = lo;
        const float4 hv = __ldg((const float4*)(x + (b * Nv + m) * Fv) + lane);
        split4(hv, hi, lo);
        *(uint2*)(p0 + 256) = hi;                 // col 128 start
        *(uint2*)(p0 + 256 + A_PLANE) = lo;
    }
    __syncthreads();

    // ---- MMA: 16m x 128n, K=256; each warp owns 16 cols ----
    const int wn = warp * 16;
    const int qr = lane >> 2, qc = (lane & 3) * 2;

    uint32_t aaddr[2], baddr[2];
    {
        const int ra = (lane & 7) + ((lane >> 3) & 1) * 8;
        const int ca = ((lane >> 4) & 1) * 16;
        #pragma unroll
        for (int p = 0; p < 2; ++p)
            aaddr[p] = smb + A_OFF + p * A_PLANE + ra * 528 + ca;
        const int rb = (lane & 7) + ((lane >> 4) & 1) * 8;
        const int cb = ((lane >> 3) & 1) * 16;
        #pragma unroll
        for (int p = 0; p < 2; ++p)
            baddr[p] = smb + p * W_PLANE + (wn + rb) * 528 + cb;
    }

    float acc[2][4];
    #pragma unroll
    for (int nf = 0; nf < 2; ++nf)
        #pragma unroll
        for (int q = 0; q < 4; ++q) acc[nf][q] = 0.f;

    #pragma unroll
    for (int ks = 0; ks < 16; ++ks) {
        const uint32_t off = ks * 32;
        uint32_t AH[4], AL[4], BH[4], BL[4];
        ldsm_x4(AH, aaddr[0] + off);
        ldsm_x4(AL, aaddr[1] + off);
        ldsm_x4(BH, baddr[0] + off);
        ldsm_x4(BL, baddr[1] + off);
        #pragma unroll
        for (int nf = 0; nf < 2; ++nf) {
            const uint32_t bh0 = BH[nf * 2], bh1 = BH[nf * 2 + 1];
            const uint32_t bl0 = BL[nf * 2], bl1 = BL[nf * 2 + 1];
            mma_bf16(acc[nf], AH, bh0, bh1);
            mma_bf16(acc[nf], AL, bh0, bh1);
            mma_bf16(acc[nf], AH, bl0, bl1);
        }
    }

    // ---- epilogue: + bias, write h1 cone (rows 0..10) to smem ----
    float* h1s = (float*)(sm + H1_OFF);   // [11][128]
    #pragma unroll
    for (int nf = 0; nf < 2; ++nf) {
        const int col = wn + nf * 8 + qc;
        const float b0 = __ldg(b_sage + col);
        const float b1 = __ldg(b_sage + col + 1);
        h1s[qr * 128 + col]     = acc[nf][0] + b0;
        h1s[qr * 128 + col + 1] = acc[nf][1] + b1;
        if (qr < 3) {
            h1s[(qr + 8) * 128 + col]     = acc[nf][2] + b0;
            h1s[(qr + 8) * 128 + col + 1] = acc[nf][3] + b1;
        }
    }
    __syncthreads();

    // ---- a2 = [mean_{s=1..10} h1s[s], h1s[0]] ----
    if (t < 128) {
        float a = 0.f;
        #pragma unroll
        for (int s = 1; s < 11; ++s) a += h1s[s * 128 + t];
        a2[t] = a * (1.0f / Kv);
        a2[128 + t] = h1s[t];
    }
    __syncthreads();

    // ---- h2[j] = a2 . W1[j,:] + b1[j]  (fp32 exact, half-dots) ----
    {
        const int j = t & 127, half = t >> 7;
        const float4* wr = (const float4*)(w_sage + 32768 + j * 256 + half * 128);
        const float4* ar = (const float4*)(a2 + half * 128);
        float s = 0.f;
        #pragma unroll
        for (int q = 0; q < 32; ++q) {
            const float4 w = __ldg(wr + q);
            const float4 a = ar[q];
            s = fmaf(a.x, w.x, s); s = fmaf(a.y, w.y, s);
            s = fmaf(a.z, w.z, s); s = fmaf(a.w, w.w, s);
        }
        red2[half][j] = s;
    }
    __syncthreads();
    if (t < 128) h2s[t] = red2[0][t] + red2[1][t] + __ldg(b_sage + 128 + t);
    __syncthreads();

    // ---- z[b,j] = h2 . l1w[j,:] + l1b[j]  (quarter-dots) ----
    {
        const int j = t & 63, q4 = t >> 6;
        const float4* wr = (const float4*)(l1w + j * 128 + q4 * 32);
        const float4* hr = (const float4*)(h2s + q4 * 32);
        float s = 0.f;
        #pragma unroll
        for (int q = 0; q < 8; ++q) {
            const float4 w = __ldg(wr + q);
            const float4 a = hr[q];
            s = fmaf(a.x, w.x, s); s = fmaf(a.y, w.y, s);
            s = fmaf(a.z, w.z, s); s = fmaf(a.w, w.w, s);
        }
        red4[q4][j] = s;
    }
    __syncthreads();
    if (t < 64)
        z[b * 64 + t] = red4[0][t] + red4[1][t] + red4[2][t] + red4[3][t] + __ldg(l1b + t);
}

// ---------------- tail: BN -> relu -> lin2 -> softmax (1 block x 1024 threads) ----------------
__global__ __launch_bounds__(1024) void tail_kernel(
    const float* __restrict__ z_in,
    const float* __restrict__ gamma, const float* __restrict__ beta,
    const float* __restrict__ l2w, const float* __restrict__ l2b,
    float* __restrict__ out)
{
    __shared__ float s_z[Bv][65];
    __shared__ float s_w[64][40];
    __shared__ float s_ps[8][64];
    __shared__ float s_pq[8][64];
    __shared__ float s_scale[64], s_shift[64];
    __shared__ float s_b2[Cv];
    const int t = threadIdx.x;

    #pragma unroll
    for (int i = 0; i < 8; ++i) {
        const int o = t + i * 1024;
        s_z[o >> 6][o & 63] = __ldg(z_in + o);
    }
    for (int o = t; o < Cv * 64; o += 1024) {
        const int c = o >> 6, j = o & 63;
        s_w[j][c] = __ldg(l2w + o);
    }
    if (t < Cv) s_b2[t] = __ldg(l2b + t);
    __syncthreads();

    if (t < 512) {
        const int col = t & 63, seg = t >> 6;
        float s = 0.f, q = 0.f;
        #pragma unroll
        for (int r = 0; r < 16; ++r) {
            const float v = s_z[seg * 16 + r][col];
            s += v; q = fmaf(v, v, q);
        }
        s_ps[seg][col] = s;
        s_pq[seg][col] = q;
    }
    __syncthreads();
    if (t < 64) {
        float s = 0.f, q = 0.f;
        #pragma unroll
        for (int g = 0; g < 8; ++g) { s += s_ps[g][t]; q += s_pq[g][t]; }
        const float mu  = s * (1.0f / Bv);
        const float var = q * (1.0f / Bv) - mu * mu;
        const float sc  = __ldg(gamma + t) * rsqrtf(var + 1e-5f);
        s_scale[t] = sc;
        s_shift[t] = __ldg(beta + t) - mu * sc;
    }
    __syncthreads();

    #pragma unroll
    for (int i = 0; i < 8; ++i) {
        const int o = t + i * 1024;
        const int b = o >> 6, j = o & 63;
        s_z[b][j] = fmaxf(s_z[b][j] * s_scale[j] + s_shift[j], 0.f);
    }
    __syncthreads();

    if (t < Bv) {
        float lg[Cv];
        #pragma unroll
        for (int c = 0; c < Cv; ++c) lg[c] = s_b2[c];
        #pragma unroll 4
        for (int j = 0; j < 64; ++j) {
            const float zj = s_z[t][j];
            #pragma unroll
            for (int c4 = 0; c4 < Cv / 4; ++c4) {
                const float4 w4 = *(const float4*)&s_w[j][c4 * 4];
                lg[c4 * 4 + 0] = fmaf(zj, w4.x, lg[c4 * 4 + 0]);
                lg[c4 * 4 + 1] = fmaf(zj, w4.y, lg[c4 * 4 + 1]);
                lg[c4 * 4 + 2] = fmaf(zj, w4.z, lg[c4 * 4 + 2]);
                lg[c4 * 4 + 3] = fmaf(zj, w4.w, lg[c4 * 4 + 3]);
            }
        }
        float m = lg[0];
        #pragma unroll
        for (int c = 1; c < Cv; ++c) m = fmaxf(m, lg[c]);
        float sum = 0.f;
        #pragma unroll
        for (int c = 0; c < Cv; ++c) { lg[c] = expf(lg[c] - m); sum += lg[c]; }
        const float r = 1.0f / sum;
        #pragma unroll
        for (int c = 0; c < Cv; ++c) out[t * Cv + c] = lg[c] * r;
    }
}

extern "C" void kernel_launch(void* const* d_in, const int* in_sizes, int n_in,
                              void* d_out, int out_size) {
    const float* x      = (const float*)d_in[0];
    const int*   neigh  = (const int*)  d_in[1];
    const float* w_sage = (const float*)d_in[2];
    const float* b_sage = (const float*)d_in[3];
    const float* l1w    = (const float*)d_in[4];
    const float* l1b    = (const float*)d_in[5];
    const float* gamma  = (const float*)d_in[6];
    const float* beta   = (const float*)d_in[7];
    const float* l2w    = (const float*)d_in[8];
    const float* l2b    = (const float*)d_in[9];
    float* out = (float*)d_out;

    cudaFuncSetAttribute(fused_kernel,
                         cudaFuncAttributeMaxDynamicSharedMemorySize, SMEM_BYTES);

    void* pz;
    cudaGetSymbolAddress(&pz, g_z);
    float* z = (float*)pz;

    fused_kernel<<<Bv, 256, SMEM_BYTES>>>(x, neigh, w_sage, b_sage, l1w, l1b, z);
    tail_kernel<<<1, 1024>>>(z, gamma, beta, l2w, l2b, out);
}

// round 11
// speedup vs baseline: 7.5889x; 1.1014x over previous
#include <cuda_runtime.h>
#include <cuda_bf16.h>
#include <math.h>
#include <stdint.h>

// Problem constants
constexpr int Bv = 128, Nv = 512, Kv = 10, Fv = 128, TFv = 256, Cv = 40;
constexpr int S2N = 11;     // cone nodes per b: {0} U neigh[b,0]

// Fused kernel dynamic smem (bytes)
constexpr int WPITCH  = 264;                 // bf16/row (528 B, LDSM conflict-free)
constexpr int W_PLANE = 128 * WPITCH * 2;    // 67584 (one split part of W0)
constexpr int A_OFF   = 2 * W_PLANE;         // 135168
constexpr int A_PLANE = 16 * WPITCH * 2;     // 8448  (16 padded rows)
constexpr int H1_OFF  = A_OFF + 2 * A_PLANE; // 152064
constexpr int SMEM_BYTES = H1_OFF + S2N * 128 * 4;  // 157696
// phase B reuses sm[0..33280) for z staging (pitch 65)

// Globals (allocation-free rule)
__device__ float g_z[Bv * 64];
__device__ unsigned int g_bar1 = 0;
__device__ unsigned int g_bar2 = 0;

// ---------------- HMMA / LDSM helpers ----------------
__device__ __forceinline__ void mma_bf16(float* c, const uint32_t* a,
                                         uint32_t b0, uint32_t b1) {
    asm volatile(
        "mma.sync.aligned.m16n8k16.row.col.f32.bf16.bf16.f32 "
        "{%0,%1,%2,%3}, {%4,%5,%6,%7}, {%8,%9}, {%0,%1,%2,%3};"
        : "+f"(c[0]), "+f"(c[1]), "+f"(c[2]), "+f"(c[3])
        : "r"(a[0]), "r"(a[1]), "r"(a[2]), "r"(a[3]), "r"(b0), "r"(b1));
}
__device__ __forceinline__ void ldsm_x4(uint32_t* r, uint32_t addr) {
    asm volatile("ldmatrix.sync.aligned.m8n8.x4.shared.b16 {%0,%1,%2,%3}, [%4];"
                 : "=r"(r[0]), "=r"(r[1]), "=r"(r[2]), "=r"(r[3]) : "r"(addr));
}
__device__ __forceinline__ uint32_t smem_u32(const void* p) {
    uint32_t a;
    asm("{ .reg .u64 t; cvta.to.shared.u64 t, %1; cvt.u32.u64 %0, t; }"
        : "=r"(a) : "l"(p));
    return a;
}
__device__ __forceinline__ void split4(const float4 v, uint2& hi, uint2& lo) {
    __nv_bfloat16 h[4], l[4];
    const float va[4] = {v.x, v.y, v.z, v.w};
    #pragma unroll
    for (int q = 0; q < 4; ++q) {
        h[q] = __float2bfloat16(va[q]);
        l[q] = __float2bfloat16(va[q] - __bfloat162float(h[q]));
    }
    hi = *(uint2*)h;
    lo = *(uint2*)l;
}

// ---------------- single fused kernel: one CTA per batch element ----------------
__global__ __launch_bounds__(256, 1) void fused_all_kernel(
    const float* __restrict__ x, const int* __restrict__ neigh,
    const float* __restrict__ w_sage, const float* __restrict__ b_sage,
    const float* __restrict__ l1w, const float* __restrict__ l1b,
    const float* __restrict__ gamma, const float* __restrict__ beta,
    const float* __restrict__ l2w, const float* __restrict__ l2b,
    float* __restrict__ z, float* __restrict__ out)
{
    extern __shared__ char sm[];
    __shared__ float a2[256];
    __shared__ float h2s[128];
    __shared__ float red2[2][128];
    __shared__ float red4[4][64];
    __shared__ float s_w[64][40];          // l2w transposed (staged pre-barrier)
    __shared__ float s_b2[Cv];
    __shared__ float s_scale[64], s_shift[64];
    __shared__ float s_r[64];
    const uint32_t smb = smem_u32(sm);
    const int t = threadIdx.x, lane = t & 31, warp = t >> 5;
    const int b = blockIdx.x;

    // ---- stage + split W0 (fp32 -> bf16 hi/lo planes), coalesced ----
    {
        const float4* src = (const float4*)w_sage;   // layer 0: 8192 float4
        #pragma unroll
        for (int i = 0; i < 32; ++i) {
            const int idx4 = t + i * 256;
            const float4 v = __ldg(src + idx4);
            const int n  = idx4 >> 6;
            const int k4 = (idx4 & 63) * 4;
            uint2 hi, lo;
            split4(v, hi, lo);
            char* p = sm + n * 528 + k4 * 2;
            *(uint2*)p = hi;
            *(uint2*)(p + W_PLANE) = lo;
        }
    }

    // ---- stage l2w transposed + l2b (used after barrier; overlaps everything) ----
    for (int o = t; o < Cv * 64; o += 256) {
        const int c = o >> 6, j = o & 63;
        s_w[j][c] = __ldg(l2w + o);
    }
    if (t < Cv) s_b2[t] = __ldg(l2b + t);

    // ---- zero padded A rows 11..15 (both planes) ----
    {
        const uint4 zz = make_uint4(0, 0, 0, 0);
        for (int o = t; o < 330; o += 256) {
            const int p = o / 165, i = o - p * 165;
            *(uint4*)(sm + A_OFF + p * A_PLANE + 11 * 528 + i * 16) = zz;
        }
    }

    // ---- gather-mean + self into A planes (11 cone rows) ----
    for (int r = warp; r < S2N; r += 8) {
        const int m = (r == 0) ? 0 : __ldg(neigh + (b * Nv) * Kv + (r - 1));
        const int* nb = neigh + (b * Nv + m) * Kv;
        float4 a4 = make_float4(0.f, 0.f, 0.f, 0.f);
        #pragma unroll
        for (int k = 0; k < Kv; ++k) {
            const int idx = __ldg(nb + k);
            const float4 v = __ldg((const float4*)(x + (b * Nv + idx) * Fv) + lane);
            a4.x += v.x; a4.y += v.y; a4.z += v.z; a4.w += v.w;
        }
        const float inv = 1.0f / Kv;
        a4 = make_float4(a4.x * inv, a4.y * inv, a4.z * inv, a4.w * inv);
        uint2 hi, lo;
        split4(a4, hi, lo);
        char* p0 = sm + A_OFF + r * 528 + lane * 8;
        *(uint2*)p0 = hi;
        *(uint2*)(p0 + A_PLANE) = lo;
        const float4 hv = __ldg((const float4*)(x + (b * Nv + m) * Fv) + lane);
        split4(hv, hi, lo);
        *(uint2*)(p0 + 256) = hi;
        *(uint2*)(p0 + 256 + A_PLANE) = lo;
    }
    __syncthreads();

    // ---- MMA: 16m x 128n, K=256; each warp owns 16 cols ----
    const int wn = warp * 16;
    const int qr = lane >> 2, qc = (lane & 3) * 2;

    uint32_t aaddr[2], baddr[2];
    {
        const int ra = (lane & 7) + ((lane >> 3) & 1) * 8;
        const int ca = ((lane >> 4) & 1) * 16;
        #pragma unroll
        for (int p = 0; p < 2; ++p)
            aaddr[p] = smb + A_OFF + p * A_PLANE + ra * 528 + ca;
        const int rb = (lane & 7) + ((lane >> 4) & 1) * 8;
        const int cb = ((lane >> 3) & 1) * 16;
        #pragma unroll
        for (int p = 0; p < 2; ++p)
            baddr[p] = smb + p * W_PLANE + (wn + rb) * 528 + cb;
    }

    float acc[2][4];
    #pragma unroll
    for (int nf = 0; nf < 2; ++nf)
        #pragma unroll
        for (int q = 0; q < 4; ++q) acc[nf][q] = 0.f;

    #pragma unroll
    for (int ks = 0; ks < 16; ++ks) {
        const uint32_t off = ks * 32;
        uint32_t AH[4], AL[4], BH[4], BL[4];
        ldsm_x4(AH, aaddr[0] + off);
        ldsm_x4(AL, aaddr[1] + off);
        ldsm_x4(BH, baddr[0] + off);
        ldsm_x4(BL, baddr[1] + off);
        #pragma unroll
        for (int nf = 0; nf < 2; ++nf) {
            const uint32_t bh0 = BH[nf * 2], bh1 = BH[nf * 2 + 1];
            const uint32_t bl0 = BL[nf * 2], bl1 = BL[nf * 2 + 1];
            mma_bf16(acc[nf], AH, bh0, bh1);
            mma_bf16(acc[nf], AL, bh0, bh1);
            mma_bf16(acc[nf], AH, bl0, bl1);
        }
    }

    // ---- epilogue: + bias, write h1 cone (rows 0..10) to smem ----
    float* h1s = (float*)(sm + H1_OFF);   // [11][128]
    #pragma unroll
    for (int nf = 0; nf < 2; ++nf) {
        const int col = wn + nf * 8 + qc;
        const float b0 = __ldg(b_sage + col);
        const float b1 = __ldg(b_sage + col + 1);
        h1s[qr * 128 + col]     = acc[nf][0] + b0;
        h1s[qr * 128 + col + 1] = acc[nf][1] + b1;
        if (qr < 3) {
            h1s[(qr + 8) * 128 + col]     = acc[nf][2] + b0;
            h1s[(qr + 8) * 128 + col + 1] = acc[nf][3] + b1;
        }
    }
    __syncthreads();

    // ---- a2 = [mean_{s=1..10} h1s[s], h1s[0]] ----
    if (t < 128) {
        float a = 0.f;
        #pragma unroll
        for (int s = 1; s < 11; ++s) a += h1s[s * 128 + t];
        a2[t] = a * (1.0f / Kv);
        a2[128 + t] = h1s[t];
    }
    __syncthreads();

    // ---- h2[j] = a2 . W1[j,:] + b1[j]  (fp32 exact, half-dots) ----
    {
        const int j = t & 127, half = t >> 7;
        const float4* wr = (const float4*)(w_sage + 32768 + j * 256 + half * 128);
        const float4* ar = (const float4*)(a2 + half * 128);
        float s = 0.f;
        #pragma unroll
        for (int q = 0; q < 32; ++q) {
            const float4 w = __ldg(wr + q);
            const float4 a = ar[q];
            s = fmaf(a.x, w.x, s); s = fmaf(a.y, w.y, s);
            s = fmaf(a.z, w.z, s); s = fmaf(a.w, w.w, s);
        }
        red2[half][j] = s;
    }
    __syncthreads();
    if (t < 128) h2s[t] = red2[0][t] + red2[1][t] + __ldg(b_sage + 128 + t);
    __syncthreads();

    // ---- z[b,j] = h2 . l1w[j,:] + l1b[j]  (quarter-dots) ----
    {
        const int j = t & 63, q4 = t >> 6;
        const float4* wr = (const float4*)(l1w + j * 128 + q4 * 32);
        const float4* hr = (const float4*)(h2s + q4 * 32);
        float s = 0.f;
        #pragma unroll
        for (int q = 0; q < 8; ++q) {
            const float4 w = __ldg(wr + q);
            const float4 a = hr[q];
            s = fmaf(a.x, w.x, s); s = fmaf(a.y, w.y, s);
            s = fmaf(a.z, w.z, s); s = fmaf(a.w, w.w, s);
        }
        red4[q4][j] = s;
    }
    __syncthreads();
    if (t < 64)
        z[b * 64 + t] = red4[0][t] + red4[1][t] + red4[2][t] + red4[3][t] + __ldg(l1b + t);

    // ================= device-wide barrier =================
    // grid=128 <= 148 SMs at 1 CTA/SM: all CTAs co-resident, spin is safe.
    __threadfence();
    __syncthreads();
    if (t == 0) {
        atomicAdd(&g_bar1, 1u);
        while (atomicAdd(&g_bar1, 0u) < (unsigned)Bv) { }
    }
    __syncthreads();
    __threadfence();

    // ================= phase B: BN stats (redundant per CTA) + own row =================
    float* s_zb = (float*)sm;   // reuse: [128][65]
    {
        const float4* zsrc = (const float4*)z;    // 2048 float4
        #pragma unroll
        for (int i = 0; i < 8; ++i) {
            const int o4 = t + i * 256;
            const float4 v = __ldg(zsrc + o4);
            const int rb = o4 >> 4, j = (o4 & 15) * 4;
            float* p = s_zb + rb * 65 + j;
            p[0] = v.x; p[1] = v.y; p[2] = v.z; p[3] = v.w;
        }
    }
    __syncthreads();

    if (t < 64) {
        float s = 0.f, q = 0.f;
        #pragma unroll 4
        for (int r = 0; r < Bv; ++r) {
            const float v = s_zb[r * 65 + t];
            s += v; q = fmaf(v, v, q);
        }
        const float mu  = s * (1.0f / Bv);
        const float var = q * (1.0f / Bv) - mu * mu;
        const float sc  = __ldg(gamma + t) * rsqrtf(var + 1e-5f);
        s_scale[t] = sc;
        s_shift[t] = __ldg(beta + t) - mu * sc;
    }
    __syncthreads();

    // relu'd own row
    if (t < 64)
        s_r[t] = fmaxf(s_zb[b * 65 + t] * s_scale[t] + s_shift[t], 0.f);
    __syncthreads();

    // warp 0: lin2 (2 cols per lane) + softmax via shuffle
    if (warp == 0) {
        float lgA = s_b2[lane < Cv ? lane : 0];
        float lgB = (lane < Cv - 32) ? s_b2[lane + 32] : 0.f;
        #pragma unroll 8
        for (int j = 0; j < 64; ++j) {
            const float zj = s_r[j];
            if (lane < Cv)      lgA = fmaf(zj, s_w[j][lane], lgA);
            if (lane < Cv - 32) lgB = fmaf(zj, s_w[j][lane + 32], lgB);
        }
        float m = (lane < Cv) ? lgA : -1e30f;
        if (lane < Cv - 32) m = fmaxf(m, lgB);
        #pragma unroll
        for (int o = 16; o > 0; o >>= 1)
            m = fmaxf(m, __shfl_xor_sync(0xFFFFFFFF, m, o));
        float eA = (lane < Cv) ? expf(lgA - m) : 0.f;
        float eB = (lane < Cv - 32) ? expf(lgB - m) : 0.f;
        float s = eA + eB;
        #pragma unroll
        for (int o = 16; o > 0; o >>= 1)
            s += __shfl_xor_sync(0xFFFFFFFF, s, o);
        const float r = 1.0f / s;
        if (lane < Cv)      out[b * Cv + lane] = eA * r;
        if (lane < Cv - 32) out[b * Cv + lane + 32] = eB * r;
    }

    // ---- reset barrier counters for next graph replay ----
    __syncthreads();
    if (t == 0) {
        if (atomicAdd(&g_bar2, 1u) == (unsigned)(Bv - 1)) {
            g_bar1 = 0u;
            g_bar2 = 0u;
            __threadfence();
        }
    }
}

extern "C" void kernel_launch(void* const* d_in, const int* in_sizes, int n_in,
                              void* d_out, int out_size) {
    const float* x      = (const float*)d_in[0];
    const int*   neigh  = (const int*)  d_in[1];
    const float* w_sage = (const float*)d_in[2];
    const float* b_sage = (const float*)d_in[3];
    const float* l1w    = (const float*)d_in[4];
    const float* l1b    = (const float*)d_in[5];
    const float* gamma  = (const float*)d_in[6];
    const float* beta   = (const float*)d_in[7];
    const float* l2w    = (const float*)d_in[8];
    const float* l2b    = (const float*)d_in[9];
    float* out = (float*)d_out;

    cudaFuncSetAttribute(fused_all_kernel,
                         cudaFuncAttributeMaxDynamicSharedMemorySize, SMEM_BYTES);

    void* pz;
    cudaGetSymbolAddress(&pz, g_z);
    float* z = (float*)pz;

    fused_all_kernel<<<Bv, 256, SMEM_BYTES>>>(x, neigh, w_sage, b_sage,
                                              l1w, l1b, gamma, beta, l2w, l2b,
                                              z, out);
}

// round 12
// speedup vs baseline: 8.2413x; 1.0860x over previous
#include <cuda_runtime.h>
#include <cuda_bf16.h>
#include <math.h>
#include <stdint.h>

// Problem constants
constexpr int Bv = 128, Nv = 512, Kv = 10, Fv = 128, TFv = 256, Cv = 40;
constexpr int S2N = 11;     // cone nodes per b: {0} U neigh[b,0]

// Fused kernel dynamic smem (bytes)
constexpr int WPITCH  = 264;                 // bf16/row (528 B, LDSM conflict-free)
constexpr int W_PLANE = 128 * WPITCH * 2;    // 67584 (one split part of W0)
constexpr int A_OFF   = 2 * W_PLANE;         // 135168
constexpr int A_PLANE = 16 * WPITCH * 2;     // 8448  (16 padded rows)
constexpr int H1_OFF  = A_OFF + 2 * A_PLANE; // 152064
constexpr int SMEM_BYTES = H1_OFF + S2N * 128 * 4;  // 157696

// Globals (allocation-free rule)
__device__ float g_sum[64];
__device__ float g_sumsq[64];
__device__ unsigned int g_bar1 = 0;
__device__ unsigned int g_bar2 = 0;

// ---------------- HMMA / LDSM helpers ----------------
__device__ __forceinline__ void mma_bf16(float* c, const uint32_t* a,
                                         uint32_t b0, uint32_t b1) {
    asm volatile(
        "mma.sync.aligned.m16n8k16.row.col.f32.bf16.bf16.f32 "
        "{%0,%1,%2,%3}, {%4,%5,%6,%7}, {%8,%9}, {%0,%1,%2,%3};"
        : "+f"(c[0]), "+f"(c[1]), "+f"(c[2]), "+f"(c[3])
        : "r"(a[0]), "r"(a[1]), "r"(a[2]), "r"(a[3]), "r"(b0), "r"(b1));
}
__device__ __forceinline__ void ldsm_x4(uint32_t* r, uint32_t addr) {
    asm volatile("ldmatrix.sync.aligned.m8n8.x4.shared.b16 {%0,%1,%2,%3}, [%4];"
                 : "=r"(r[0]), "=r"(r[1]), "=r"(r[2]), "=r"(r[3]) : "r"(addr));
}
__device__ __forceinline__ uint32_t smem_u32(const void* p) {
    uint32_t a;
    asm("{ .reg .u64 t; cvta.to.shared.u64 t, %1; cvt.u32.u64 %0, t; }"
        : "=r"(a) : "l"(p));
    return a;
}
__device__ __forceinline__ void split4(const float4 v, uint2& hi, uint2& lo) {
    __nv_bfloat16 h[4], l[4];
    const float va[4] = {v.x, v.y, v.z, v.w};
    #pragma unroll
    for (int q = 0; q < 4; ++q) {
        h[q] = __float2bfloat16(va[q]);
        l[q] = __float2bfloat16(va[q] - __bfloat162float(h[q]));
    }
    hi = *(uint2*)h;
    lo = *(uint2*)l;
}

// ---------------- single fused kernel: one CTA per batch element ----------------
__global__ __launch_bounds__(256, 1) void fused_all_kernel(
    const float* __restrict__ x, const int* __restrict__ neigh,
    const float* __restrict__ w_sage, const float* __restrict__ b_sage,
    const float* __restrict__ l1w, const float* __restrict__ l1b,
    const float* __restrict__ gamma, const float* __restrict__ beta,
    const float* __restrict__ l2w, const float* __restrict__ l2b,
    float* __restrict__ out)
{
    extern __shared__ char sm[];
    __shared__ float a2[256];
    __shared__ float h2s[128];
    __shared__ float red2[2][128];
    __shared__ float red4[4][64];
    __shared__ float s_w[64][40];          // l2w transposed (staged pre-barrier)
    __shared__ float s_b2[Cv];
    __shared__ float s_r[64];              // this CTA's z row -> relu'd row
    const uint32_t smb = smem_u32(sm);
    const int t = threadIdx.x, lane = t & 31, warp = t >> 5;
    const int b = blockIdx.x;

    // ---- stage + split W0 (fp32 -> bf16 hi/lo planes), coalesced ----
    {
        const float4* src = (const float4*)w_sage;   // layer 0: 8192 float4
        #pragma unroll
        for (int i = 0; i < 32; ++i) {
            const int idx4 = t + i * 256;
            const float4 v = __ldg(src + idx4);
            const int n  = idx4 >> 6;
            const int k4 = (idx4 & 63) * 4;
            uint2 hi, lo;
            split4(v, hi, lo);
            char* p = sm + n * 528 + k4 * 2;
            *(uint2*)p = hi;
            *(uint2*)(p + W_PLANE) = lo;
        }
    }

    // ---- stage l2w transposed + l2b (used after barrier; overlaps everything) ----
    for (int o = t; o < Cv * 64; o += 256) {
        const int c = o >> 6, j = o & 63;
        s_w[j][c] = __ldg(l2w + o);
    }
    if (t < Cv) s_b2[t] = __ldg(l2b + t);

    // ---- zero padded A rows 11..15 (both planes) ----
    {
        const uint4 zz = make_uint4(0, 0, 0, 0);
        for (int o = t; o < 330; o += 256) {
            const int p = o / 165, i = o - p * 165;
            *(uint4*)(sm + A_OFF + p * A_PLANE + 11 * 528 + i * 16) = zz;
        }
    }

    // ---- gather-mean + self into A planes (11 cone rows) ----
    for (int r = warp; r < S2N; r += 8) {
        const int m = (r == 0) ? 0 : __ldg(neigh + (b * Nv) * Kv + (r - 1));
        const int* nb = neigh + (b * Nv + m) * Kv;
        float4 a4 = make_float4(0.f, 0.f, 0.f, 0.f);
        #pragma unroll
        for (int k = 0; k < Kv; ++k) {
            const int idx = __ldg(nb + k);
            const float4 v = __ldg((const float4*)(x + (b * Nv + idx) * Fv) + lane);
            a4.x += v.x; a4.y += v.y; a4.z += v.z; a4.w += v.w;
        }
        const float inv = 1.0f / Kv;
        a4 = make_float4(a4.x * inv, a4.y * inv, a4.z * inv, a4.w * inv);
        uint2 hi, lo;
        split4(a4, hi, lo);
        char* p0 = sm + A_OFF + r * 528 + lane * 8;
        *(uint2*)p0 = hi;
        *(uint2*)(p0 + A_PLANE) = lo;
        const float4 hv = __ldg((const float4*)(x + (b * Nv + m) * Fv) + lane);
        split4(hv, hi, lo);
        *(uint2*)(p0 + 256) = hi;
        *(uint2*)(p0 + 256 + A_PLANE) = lo;
    }
    __syncthreads();

    // ---- MMA: 16m x 128n, K=256; each warp owns 16 cols ----
    const int wn = warp * 16;
    const int qr = lane >> 2, qc = (lane & 3) * 2;

    uint32_t aaddr[2], baddr[2];
    {
        const int ra = (lane & 7) + ((lane >> 3) & 1) * 8;
        const int ca = ((lane >> 4) & 1) * 16;
        #pragma unroll
        for (int p = 0; p < 2; ++p)
            aaddr[p] = smb + A_OFF + p * A_PLANE + ra * 528 + ca;
        const int rb = (lane & 7) + ((lane >> 4) & 1) * 8;
        const int cb = ((lane >> 3) & 1) * 16;
        #pragma unroll
        for (int p = 0; p < 2; ++p)
            baddr[p] = smb + p * W_PLANE + (wn + rb) * 528 + cb;
    }

    float acc[2][4];
    #pragma unroll
    for (int nf = 0; nf < 2; ++nf)
        #pragma unroll
        for (int q = 0; q < 4; ++q) acc[nf][q] = 0.f;

    #pragma unroll
    for (int ks = 0; ks < 16; ++ks) {
        const uint32_t off = ks * 32;
        uint32_t AH[4], AL[4], BH[4], BL[4];
        ldsm_x4(AH, aaddr[0] + off);
        ldsm_x4(AL, aaddr[1] + off);
        ldsm_x4(BH, baddr[0] + off);
        ldsm_x4(BL, baddr[1] + off);
        #pragma unroll
        for (int nf = 0; nf < 2; ++nf) {
            const uint32_t bh0 = BH[nf * 2], bh1 = BH[nf * 2 + 1];
            const uint32_t bl0 = BL[nf * 2], bl1 = BL[nf * 2 + 1];
            mma_bf16(acc[nf], AH, bh0, bh1);
            mma_bf16(acc[nf], AL, bh0, bh1);
            mma_bf16(acc[nf], AH, bl0, bl1);
        }
    }

    // ---- epilogue: + bias, write h1 cone (rows 0..10) to smem ----
    float* h1s = (float*)(sm + H1_OFF);   // [11][128]
    #pragma unroll
    for (int nf = 0; nf < 2; ++nf) {
        const int col = wn + nf * 8 + qc;
        const float b0 = __ldg(b_sage + col);
        const float b1 = __ldg(b_sage + col + 1);
        h1s[qr * 128 + col]     = acc[nf][0] + b0;
        h1s[qr * 128 + col + 1] = acc[nf][1] + b1;
        if (qr < 3) {
            h1s[(qr + 8) * 128 + col]     = acc[nf][2] + b0;
            h1s[(qr + 8) * 128 + col + 1] = acc[nf][3] + b1;
        }
    }
    __syncthreads();

    // ---- a2 = [mean_{s=1..10} h1s[s], h1s[0]] ----
    if (t < 128) {
        float a = 0.f;
        #pragma unroll
        for (int s = 1; s < 11; ++s) a += h1s[s * 128 + t];
        a2[t] = a * (1.0f / Kv);
        a2[128 + t] = h1s[t];
    }
    __syncthreads();

    // ---- h2[j] = a2 . W1[j,:] + b1[j]  (fp32 exact, 4-acc chain break) ----
    {
        const int j = t & 127, half = t >> 7;
        const float4* wr = (const float4*)(w_sage + 32768 + j * 256 + half * 128);
        const float4* ar = (const float4*)(a2 + half * 128);
        float s0 = 0.f, s1 = 0.f, s2 = 0.f, s3 = 0.f;
        #pragma unroll
        for (int q = 0; q < 32; q += 4) {
            const float4 w0 = __ldg(wr + q),     a0 = ar[q];
            const float4 w1 = __ldg(wr + q + 1), a1 = ar[q + 1];
            const float4 w2 = __ldg(wr + q + 2), a2v = ar[q + 2];
            const float4 w3 = __ldg(wr + q + 3), a3 = ar[q + 3];
            s0 = fmaf(a0.x, w0.x, s0); s0 = fmaf(a0.y, w0.y, s0);
            s0 = fmaf(a0.z, w0.z, s0); s0 = fmaf(a0.w, w0.w, s0);
            s1 = fmaf(a1.x, w1.x, s1); s1 = fmaf(a1.y, w1.y, s1);
            s1 = fmaf(a1.z, w1.z, s1); s1 = fmaf(a1.w, w1.w, s1);
            s2 = fmaf(a2v.x, w2.x, s2); s2 = fmaf(a2v.y, w2.y, s2);
            s2 = fmaf(a2v.z, w2.z, s2); s2 = fmaf(a2v.w, w2.w, s2);
            s3 = fmaf(a3.x, w3.x, s3); s3 = fmaf(a3.y, w3.y, s3);
            s3 = fmaf(a3.z, w3.z, s3); s3 = fmaf(a3.w, w3.w, s3);
        }
        red2[half][j] = (s0 + s1) + (s2 + s3);
    }
    __syncthreads();
    if (t < 128) h2s[t] = red2[0][t] + red2[1][t] + __ldg(b_sage + 128 + t);
    __syncthreads();

    // ---- z[b,j] = h2 . l1w[j,:] + l1b[j]  (quarter-dots, 2 accs) ----
    {
        const int j = t & 63, q4 = t >> 6;
        const float4* wr = (const float4*)(l1w + j * 128 + q4 * 32);
        const float4* hr = (const float4*)(h2s + q4 * 32);
        float s0 = 0.f, s1 = 0.f;
        #pragma unroll
        for (int q = 0; q < 8; q += 2) {
            const float4 w0 = __ldg(wr + q),     a0 = hr[q];
            const float4 w1 = __ldg(wr + q + 1), a1 = hr[q + 1];
            s0 = fmaf(a0.x, w0.x, s0); s0 = fmaf(a0.y, w0.y, s0);
            s0 = fmaf(a0.z, w0.z, s0); s0 = fmaf(a0.w, w0.w, s0);
            s1 = fmaf(a1.x, w1.x, s1); s1 = fmaf(a1.y, w1.y, s1);
            s1 = fmaf(a1.z, w1.z, s1); s1 = fmaf(a1.w, w1.w, s1);
        }
        red4[q4][j] = s0 + s1;
    }
    __syncthreads();

    // ---- own z row -> smem + atomic global BN accumulators ----
    if (t < 64) {
        const float zv = red4[0][t] + red4[1][t] + red4[2][t] + red4[3][t]
                       + __ldg(l1b + t);
        s_r[t] = zv;
        atomicAdd(&g_sum[t], zv);
        atomicAdd(&g_sumsq[t], zv * zv);
    }

    // ================= device-wide barrier =================
    // grid=128 <= 148 SMs at 1 CTA/SM: all CTAs co-resident, spin is safe.
    __threadfence();
    __syncthreads();
    if (t == 0) {
        atomicAdd(&g_bar1, 1u);
        while (atomicAdd(&g_bar1, 0u) < (unsigned)Bv) { }
    }
    __syncthreads();

    // ================= phase B: finish own row only =================
    if (t < 64) {
        const float s  = __ldcg(&g_sum[t]);       // .cg: bypass L1, read L2
        const float q  = __ldcg(&g_sumsq[t]);
        const float mu  = s * (1.0f / Bv);
        const float var = q * (1.0f / Bv) - mu * mu;
        const float sc  = __ldg(gamma + t) * rsqrtf(var + 1e-5f);
        const float sh  = __ldg(beta + t) - mu * sc;
        s_r[t] = fmaxf(s_r[t] * sc + sh, 0.f);
    }
    __syncthreads();

    // warp 0: lin2 (2 cols per lane) + softmax via shuffle
    if (warp == 0) {
        float lgA = s_b2[lane];                       // lane < 32 < Cv
        float lgB = (lane < Cv - 32) ? s_b2[lane + 32] : 0.f;
        #pragma unroll 8
        for (int j = 0; j < 64; ++j) {
            const float zj = s_r[j];
            lgA = fmaf(zj, s_w[j][lane], lgA);
            if (lane < Cv - 32) lgB = fmaf(zj, s_w[j][lane + 32], lgB);
        }
        float m = lgA;
        if (lane < Cv - 32) m = fmaxf(m, lgB);
        #pragma unroll
        for (int o = 16; o > 0; o >>= 1)
            m = fmaxf(m, __shfl_xor_sync(0xFFFFFFFF, m, o));
        float eA = expf(lgA - m);
        float eB = (lane < Cv - 32) ? expf(lgB - m) : 0.f;
        float s = eA + eB;
        #pragma unroll
        for (int o = 16; o > 0; o >>= 1)
            s += __shfl_xor_sync(0xFFFFFFFF, s, o);
        const float r = 1.0f / s;
        out[b * Cv + lane] = eA * r;
        if (lane < Cv - 32) out[b * Cv + lane + 32] = eB * r;
    }

    // ---- reset counters/accumulators for next graph replay ----
    __syncthreads();   // all readers of g_sum/g_sumsq are done in this CTA
    if (t == 0) {
        if (atomicAdd(&g_bar2, 1u) == (unsigned)(Bv - 1)) {
            // last CTA out: everyone has passed the spin and finished reads
            #pragma unroll
            for (int j = 0; j < 64; ++j) { g_sum[j] = 0.f; g_sumsq[j] = 0.f; }
            g_bar1 = 0u;
            g_bar2 = 0u;
            __threadfence();
        }
    }
}

extern "C" void kernel_launch(void* const* d_in, const int* in_sizes, int n_in,
                              void* d_out, int out_size) {
    const float* x      = (const float*)d_in[0];
    const int*   neigh  = (const int*)  d_in[1];
    const float* w_sage = (const float*)d_in[2];
    const float* b_sage = (const float*)d_in[3];
    const float* l1w    = (const float*)d_in[4];
    const float* l1b    = (const float*)d_in[5];
    const float* gamma  = (const float*)d_in[6];
    const float* beta   = (const float*)d_in[7];
    const float* l2w    = (const float*)d_in[8];
    const float* l2b    = (const float*)d_in[9];
    float* out = (float*)d_out;

    cudaFuncSetAttribute(fused_all_kernel,
                         cudaFuncAttributeMaxDynamicSharedMemorySize, SMEM_BYTES);

    fused_all_kernel<<<Bv, 256, SMEM_BYTES>>>(x, neigh, w_sage, b_sage,
                                              l1w, l1b, gamma, beta, l2w, l2b,
                                              out);
}

// round 13
// speedup vs baseline: 9.2142x; 1.1180x over previous
#include <cuda_runtime.h>
#include <cuda_bf16.h>
#include <math.h>
#include <stdint.h>

// Problem constants
constexpr int Bv = 128, Nv = 512, Kv = 10, Fv = 128, TFv = 256, Cv = 40;
constexpr int S2N = 11;     // cone nodes per b: {0} U neigh[b,0]
constexpr int THREADS = 512;

// Fused kernel dynamic smem (bytes)
constexpr int WPITCH  = 264;                 // bf16/row (528 B, LDSM conflict-free)
constexpr int W_PLANE = 128 * WPITCH * 2;    // 67584 (one split part of W0)
constexpr int A_OFF   = 2 * W_PLANE;         // 135168
constexpr int A_PLANE = 16 * WPITCH * 2;     // 8448  (16 padded rows)
constexpr int H1_OFF  = A_OFF + 2 * A_PLANE; // 152064
constexpr int SMEM_BYTES = H1_OFF + S2N * 128 * 4;  // 157696

// Globals (allocation-free rule)
__device__ float g_sum[64];
__device__ float g_sumsq[64];
__device__ unsigned int g_bar1 = 0;
__device__ unsigned int g_bar2 = 0;

// ---------------- HMMA / LDSM helpers ----------------
__device__ __forceinline__ void mma_bf16(float* c, const uint32_t* a,
                                         uint32_t b0, uint32_t b1) {
    asm volatile(
        "mma.sync.aligned.m16n8k16.row.col.f32.bf16.bf16.f32 "
        "{%0,%1,%2,%3}, {%4,%5,%6,%7}, {%8,%9}, {%0,%1,%2,%3};"
        : "+f"(c[0]), "+f"(c[1]), "+f"(c[2]), "+f"(c[3])
        : "r"(a[0]), "r"(a[1]), "r"(a[2]), "r"(a[3]), "r"(b0), "r"(b1));
}
__device__ __forceinline__ void ldsm_x4(uint32_t* r, uint32_t addr) {
    asm volatile("ldmatrix.sync.aligned.m8n8.x4.shared.b16 {%0,%1,%2,%3}, [%4];"
                 : "=r"(r[0]), "=r"(r[1]), "=r"(r[2]), "=r"(r[3]) : "r"(addr));
}
__device__ __forceinline__ uint32_t smem_u32(const void* p) {
    uint32_t a;
    asm("{ .reg .u64 t; cvta.to.shared.u64 t, %1; cvt.u32.u64 %0, t; }"
        : "=r"(a) : "l"(p));
    return a;
}
__device__ __forceinline__ void split4(const float4 v, uint2& hi, uint2& lo) {
    __nv_bfloat16 h[4], l[4];
    const float va[4] = {v.x, v.y, v.z, v.w};
    #pragma unroll
    for (int q = 0; q < 4; ++q) {
        h[q] = __float2bfloat16(va[q]);
        l[q] = __float2bfloat16(va[q] - __bfloat162float(h[q]));
    }
    hi = *(uint2*)h;
    lo = *(uint2*)l;
}

// ---------------- single fused kernel: one CTA per batch element ----------------
__global__ __launch_bounds__(THREADS, 1) void fused_all_kernel(
    const float* __restrict__ x, const int* __restrict__ neigh,
    const float* __restrict__ w_sage, const float* __restrict__ b_sage,
    const float* __restrict__ l1w, const float* __restrict__ l1b,
    const float* __restrict__ gamma, const float* __restrict__ beta,
    const float* __restrict__ l2w, const float* __restrict__ l2b,
    float* __restrict__ out)
{
    extern __shared__ char sm[];
    __shared__ float a2[256];
    __shared__ float h2s[128];
    __shared__ float redh[4][128];         // h2 GEMV partials
    __shared__ float redl[8][64];          // lin1 partials
    __shared__ float s_w[64][40];          // l2w transposed (staged pre-barrier)
    __shared__ float s_b2[Cv];
    __shared__ float s_r[64];              // this CTA's z row -> relu'd row
    const uint32_t smb = smem_u32(sm);
    const int t = threadIdx.x, lane = t & 31, warp = t >> 5;
    const int b = blockIdx.x;

    // ---- stage + split W0 (fp32 -> bf16 hi/lo planes), coalesced, 16 rounds ----
    {
        const float4* src = (const float4*)w_sage;   // layer 0: 8192 float4
        #pragma unroll
        for (int i = 0; i < 16; ++i) {
            const int idx4 = t + i * THREADS;
            const float4 v = __ldg(src + idx4);
            const int n  = idx4 >> 6;
            const int k4 = (idx4 & 63) * 4;
            uint2 hi, lo;
            split4(v, hi, lo);
            char* p = sm + n * 528 + k4 * 2;
            *(uint2*)p = hi;
            *(uint2*)(p + W_PLANE) = lo;
        }
    }

    // ---- stage l2w transposed + l2b (used after barrier) ----
    for (int o = t; o < Cv * 64; o += THREADS) {
        const int c = o >> 6, j = o & 63;
        s_w[j][c] = __ldg(l2w + o);
    }
    if (t < Cv) s_b2[t] = __ldg(l2b + t);

    // ---- zero padded A rows 11..15 (both planes) ----
    if (t < 330) {
        const uint4 zz = make_uint4(0, 0, 0, 0);
        const int p = t / 165, i = t - p * 165;
        *(uint4*)(sm + A_OFF + p * A_PLANE + 11 * 528 + i * 16) = zz;
    }

    // ---- gather-mean + self into A planes: one row per warp, single round ----
    if (warp < S2N) {
        const int r = warp;
        const int m = (r == 0) ? 0 : __ldg(neigh + (b * Nv) * Kv + (r - 1));
        const int* nb = neigh + (b * Nv + m) * Kv;
        float4 a4 = make_float4(0.f, 0.f, 0.f, 0.f);
        #pragma unroll
        for (int k = 0; k < Kv; ++k) {
            const int idx = __ldg(nb + k);
            const float4 v = __ldg((const float4*)(x + (b * Nv + idx) * Fv) + lane);
            a4.x += v.x; a4.y += v.y; a4.z += v.z; a4.w += v.w;
        }
        const float inv = 1.0f / Kv;
        a4 = make_float4(a4.x * inv, a4.y * inv, a4.z * inv, a4.w * inv);
        uint2 hi, lo;
        split4(a4, hi, lo);
        char* p0 = sm + A_OFF + r * 528 + lane * 8;
        *(uint2*)p0 = hi;
        *(uint2*)(p0 + A_PLANE) = lo;
        const float4 hv = __ldg((const float4*)(x + (b * Nv + m) * Fv) + lane);
        split4(hv, hi, lo);
        *(uint2*)(p0 + 256) = hi;
        *(uint2*)(p0 + 256 + A_PLANE) = lo;
    }
    __syncthreads();

    // ---- MMA: warps 0-7 only; 16m x 128n, K=256; each warp owns 16 cols ----
    const int qr = lane >> 2, qc = (lane & 3) * 2;
    if (warp < 8) {
        const int wn = warp * 16;
        uint32_t aaddr[2], baddr[2];
        {
            const int ra = (lane & 7) + ((lane >> 3) & 1) * 8;
            const int ca = ((lane >> 4) & 1) * 16;
            #pragma unroll
            for (int p = 0; p < 2; ++p)
                aaddr[p] = smb + A_OFF + p * A_PLANE + ra * 528 + ca;
            const int rb = (lane & 7) + ((lane >> 4) & 1) * 8;
            const int cb = ((lane >> 3) & 1) * 16;
            #pragma unroll
            for (int p = 0; p < 2; ++p)
                baddr[p] = smb + p * W_PLANE + (wn + rb) * 528 + cb;
        }

        float acc[2][4];
        #pragma unroll
        for (int nf = 0; nf < 2; ++nf)
            #pragma unroll
            for (int q = 0; q < 4; ++q) acc[nf][q] = 0.f;

        #pragma unroll
        for (int ks = 0; ks < 16; ++ks) {
            const uint32_t off = ks * 32;
            uint32_t AH[4], AL[4], BH[4], BL[4];
            ldsm_x4(AH, aaddr[0] + off);
            ldsm_x4(AL, aaddr[1] + off);
            ldsm_x4(BH, baddr[0] + off);
            ldsm_x4(BL, baddr[1] + off);
            #pragma unroll
            for (int nf = 0; nf < 2; ++nf) {
                const uint32_t bh0 = BH[nf * 2], bh1 = BH[nf * 2 + 1];
                const uint32_t bl0 = BL[nf * 2], bl1 = BL[nf * 2 + 1];
                mma_bf16(acc[nf], AH, bh0, bh1);
                mma_bf16(acc[nf], AL, bh0, bh1);
                mma_bf16(acc[nf], AH, bl0, bl1);
            }
        }

        // epilogue: + bias, write h1 cone (rows 0..10) to smem
        float* h1s = (float*)(sm + H1_OFF);   // [11][128]
        #pragma unroll
        for (int nf = 0; nf < 2; ++nf) {
            const int col = wn + nf * 8 + qc;
            const float b0 = __ldg(b_sage + col);
            const float b1 = __ldg(b_sage + col + 1);
            h1s[qr * 128 + col]     = acc[nf][0] + b0;
            h1s[qr * 128 + col + 1] = acc[nf][1] + b1;
            if (qr < 3) {
                h1s[(qr + 8) * 128 + col]     = acc[nf][2] + b0;
                h1s[(qr + 8) * 128 + col + 1] = acc[nf][3] + b1;
            }
        }
    }
    __syncthreads();

    // ---- a2 = [mean_{s=1..10} h1s[s], h1s[0]] ----
    {
        float* h1s = (float*)(sm + H1_OFF);
        if (t < 128) {
            float a = 0.f;
            #pragma unroll
            for (int s = 1; s < 11; ++s) a += h1s[s * 128 + t];
            a2[t] = a * (1.0f / Kv);
            a2[128 + t] = h1s[t];
        }
    }
    __syncthreads();

    // ---- h2[j] = a2 . W1[j,:] + b1[j]  (fp32 exact, 4-way split, 2 accs) ----
    {
        const int j = t & 127, qtr = t >> 7;     // 4 quarters of 64 k each
        const float4* wr = (const float4*)(w_sage + 32768 + j * 256 + qtr * 64);
        const float4* ar = (const float4*)(a2 + qtr * 64);
        float s0 = 0.f, s1 = 0.f;
        #pragma unroll
        for (int q = 0; q < 16; q += 2) {
            const float4 w0 = __ldg(wr + q),     a0 = ar[q];
            const float4 w1 = __ldg(wr + q + 1), a1 = ar[q + 1];
            s0 = fmaf(a0.x, w0.x, s0); s0 = fmaf(a0.y, w0.y, s0);
            s0 = fmaf(a0.z, w0.z, s0); s0 = fmaf(a0.w, w0.w, s0);
            s1 = fmaf(a1.x, w1.x, s1); s1 = fmaf(a1.y, w1.y, s1);
            s1 = fmaf(a1.z, w1.z, s1); s1 = fmaf(a1.w, w1.w, s1);
        }
        redh[qtr][j] = s0 + s1;
    }
    __syncthreads();
    if (t < 128)
        h2s[t] = (redh[0][t] + redh[1][t]) + (redh[2][t] + redh[3][t])
               + __ldg(b_sage + 128 + t);
    __syncthreads();

    // ---- z[b,j] = h2 . l1w[j,:] + l1b[j]  (8-way split) ----
    {
        const int j = t & 63, seg = t >> 6;      // 8 segments of 16 k each
        const float4* wr = (const float4*)(l1w + j * 128 + seg * 16);
        const float4* hr = (const float4*)(h2s + seg * 16);
        float s0 = 0.f, s1 = 0.f;
        {
            const float4 w0 = __ldg(wr + 0), a0 = hr[0];
            const float4 w1 = __ldg(wr + 1), a1 = hr[1];
            const float4 w2 = __ldg(wr + 2), a2v = hr[2];
            const float4 w3 = __ldg(wr + 3), a3 = hr[3];
            s0 = fmaf(a0.x, w0.x, s0); s0 = fmaf(a0.y, w0.y, s0);
            s0 = fmaf(a0.z, w0.z, s0); s0 = fmaf(a0.w, w0.w, s0);
            s1 = fmaf(a1.x, w1.x, s1); s1 = fmaf(a1.y, w1.y, s1);
            s1 = fmaf(a1.z, w1.z, s1); s1 = fmaf(a1.w, w1.w, s1);
            s0 = fmaf(a2v.x, w2.x, s0); s0 = fmaf(a2v.y, w2.y, s0);
            s0 = fmaf(a2v.z, w2.z, s0); s0 = fmaf(a2v.w, w2.w, s0);
            s1 = fmaf(a3.x, w3.x, s1); s1 = fmaf(a3.y, w3.y, s1);
            s1 = fmaf(a3.z, w3.z, s1); s1 = fmaf(a3.w, w3.w, s1);
        }
        redl[seg][j] = s0 + s1;
    }
    __syncthreads();

    // ---- own z row -> smem + atomic global BN accumulators ----
    if (t < 64) {
        float zv = __ldg(l1b + t);
        #pragma unroll
        for (int g = 0; g < 8; ++g) zv += redl[g][t];
        s_r[t] = zv;
        atomicAdd(&g_sum[t], zv);
        atomicAdd(&g_sumsq[t], zv * zv);
    }

    // ================= device-wide barrier =================
    // grid=128 <= 148 SMs at 1 CTA/SM: all CTAs co-resident, spin is safe.
    __threadfence();
    __syncthreads();
    if (t == 0) {
        atomicAdd(&g_bar1, 1u);
        while (atomicAdd(&g_bar1, 0u) < (unsigned)Bv) { }
    }
    __syncthreads();

    // ================= phase B: finish own row only =================
    if (t < 64) {
        const float s  = __ldcg(&g_sum[t]);       // .cg: bypass L1, read L2
        const float q  = __ldcg(&g_sumsq[t]);
        const float mu  = s * (1.0f / Bv);
        const float var = q * (1.0f / Bv) - mu * mu;
        const float sc  = __ldg(gamma + t) * rsqrtf(var + 1e-5f);
        const float sh  = __ldg(beta + t) - mu * sc;
        s_r[t] = fmaxf(s_r[t] * sc + sh, 0.f);
    }
    __syncthreads();

    // warp 0: lin2 (2 cols per lane) + softmax via shuffle
    if (warp == 0) {
        float lgA = s_b2[lane];                       // lane < 32 < Cv
        float lgB = (lane < Cv - 32) ? s_b2[lane + 32] : 0.f;
        #pragma unroll 8
        for (int j = 0; j < 64; ++j) {
            const float zj = s_r[j];
            lgA = fmaf(zj, s_w[j][lane], lgA);
            if (lane < Cv - 32) lgB = fmaf(zj, s_w[j][lane + 32], lgB);
        }
        float m = lgA;
        if (lane < Cv - 32) m = fmaxf(m, lgB);
        #pragma unroll
        for (int o = 16; o > 0; o >>= 1)
            m = fmaxf(m, __shfl_xor_sync(0xFFFFFFFF, m, o));
        float eA = expf(lgA - m);
        float eB = (lane < Cv - 32) ? expf(lgB - m) : 0.f;
        float s = eA + eB;
        #pragma unroll
        for (int o = 16; o > 0; o >>= 1)
            s += __shfl_xor_sync(0xFFFFFFFF, s, o);
        const float r = 1.0f / s;
        out[b * Cv + lane] = eA * r;
        if (lane < Cv - 32) out[b * Cv + lane + 32] = eB * r;
    }

    // ---- reset counters/accumulators for next graph replay ----
    __syncthreads();   // all readers of g_sum/g_sumsq are done in this CTA
    if (t == 0) {
        if (atomicAdd(&g_bar2, 1u) == (unsigned)(Bv - 1)) {
            #pragma unroll
            for (int j = 0; j < 64; ++j) { g_sum[j] = 0.f; g_sumsq[j] = 0.f; }
            g_bar1 = 0u;
            g_bar2 = 0u;
            __threadfence();
        }
    }
}

extern "C" void kernel_launch(void* const* d_in, const int* in_sizes, int n_in,
                              void* d_out, int out_size) {
    const float* x      = (const float*)d_in[0];
    const int*   neigh  = (const int*)  d_in[1];
    const float* w_sage = (const float*)d_in[2];
    const float* b_sage = (const float*)d_in[3];
    const float* l1w    = (const float*)d_in[4];
    const float* l1b    = (const float*)d_in[5];
    const float* gamma  = (const float*)d_in[6];
    const float* beta   = (const float*)d_in[7];
    const float* l2w    = (const float*)d_in[8];
    const float* l2b    = (const float*)d_in[9];
    float* out = (float*)d_out;

    cudaFuncSetAttribute(fused_all_kernel,
                         cudaFuncAttributeMaxDynamicSharedMemorySize, SMEM_BYTES);

    fused_all_kernel<<<Bv, THREADS, SMEM_BYTES>>>(x, neigh, w_sage, b_sage,
                                                  l1w, l1b, gamma, beta, l2w, l2b,
                                                  out);
}